// round 9
// baseline (speedup 1.0000x reference)
#include <cuda_runtime.h>
#include <cuda_fp16.h>
#include <math.h>
#include <float.h>
#include <stdint.h>

// ---------------- problem constants ----------------
#define B_ROWS   1024
#define EMB_D    512
#define NCLASS   100000
#define CT       128                              // class tile (N)
#define NTILES   ((NCLASS + CT - 1) / CT)         // 782
#define SCALE_F  30.0f

#define TILES_PER_CTA 4
#define STRIPS   196                              // 196*4 = 784 >= 782

// ArcFace margin constants (margin = 0.3)
#define COS_M 0.9553364891256061f
#define SIN_M 0.2955202066613396f
#define TH_C  (-0.9553364891256061f)
#define MM_C  0.08865606199840186f

// ---------------- scratch ----------------
__device__ __half g_wh[(size_t)NCLASS * EMB_D];   // fp16 weight, 30/||w|| folded
__device__ __half g_eh[B_ROWS * EMB_D];           // fp16 embeddings
__device__ float  g_inv_norm[NCLASS];             // 30/||w|| (exact label path)
__device__ float  g_m[B_ROWS * NTILES];
__device__ float  g_s[B_ROWS * NTILES];
__device__ float  g_nll[B_ROWS];
__device__ int    g_lab_is64;

// ---------------- helpers ----------------
__device__ __forceinline__ uint32_t smem_u32(const void* p) {
    uint32_t a;
    asm("{ .reg .u64 t; cvta.to.shared.u64 t, %1; cvt.u32.u64 %0, t; }" : "=r"(a) : "l"(p));
    return a;
}
__device__ __forceinline__ void cp16(uint32_t dst, const void* src, int bytes) {
    asm volatile("cp.async.cg.shared.global [%0], [%1], 16, %2;" :: "r"(dst), "l"(src), "r"(bytes));
}
#define CP_COMMIT()  asm volatile("cp.async.commit_group;" ::: "memory")
#define CP_WAIT(n)   asm volatile("cp.async.wait_group %0;" :: "n"(n) : "memory")

__device__ __forceinline__ void mma_16816(float* c, const uint32_t* a, uint32_t b0, uint32_t b1) {
    asm volatile(
        "mma.sync.aligned.m16n8k16.row.col.f32.f16.f16.f32 "
        "{%0,%1,%2,%3}, {%4,%5,%6,%7}, {%8,%9}, {%0,%1,%2,%3};"
        : "+f"(c[0]), "+f"(c[1]), "+f"(c[2]), "+f"(c[3])
        : "r"(a[0]), "r"(a[1]), "r"(a[2]), "r"(a[3]), "r"(b0), "r"(b1));
}
__device__ __forceinline__ void ldm_x4(uint32_t* r, uint32_t addr) {
    asm volatile("ldmatrix.sync.aligned.m8n8.x4.shared.b16 {%0,%1,%2,%3}, [%4];"
                 : "=r"(r[0]), "=r"(r[1]), "=r"(r[2]), "=r"(r[3]) : "r"(addr));
}

// smem geometry: fp16, K-chunk 64, padded row stride 72 halves (144 B)
// stage = A(256 rows) + B(128 rows)
#define RS_H        72
#define A_ROWS      256
#define B_ROWS_T    128
#define A_TILE_B    (A_ROWS * RS_H * 2)            // 36864
#define B_TILE_B    (B_ROWS_T * RS_H * 2)          // 18432
#define STAGE_B     (A_TILE_B + B_TILE_B)          // 55296
#define SMEM_DYN    (2 * STAGE_B + 4096)           // 2 stages + partials

// ---------------------------------------------------------------------------
// Kernel A: probe labels dtype (int64 vs int32 under JAX x64-off).
// ---------------------------------------------------------------------------
__global__ __launch_bounds__(512) void detect_labels_kernel(const void* __restrict__ labels) {
    __shared__ int bad;
    if (threadIdx.x == 0) bad = 0;
    __syncthreads();
    long long v = ((const long long*)labels)[threadIdx.x];
    if (v < 0 || v >= NCLASS) atomicOr(&bad, 1);
    __syncthreads();
    if (threadIdx.x == 0) g_lab_is64 = bad ? 0 : 1;
}

// ---------------------------------------------------------------------------
// Kernel 0: fused per-class norm + fp16 convert (30/||w|| folded).
// ---------------------------------------------------------------------------
__global__ __launch_bounds__(256) void norm_convert_w(const float* __restrict__ weight) {
    int gid  = blockIdx.x * blockDim.x + threadIdx.x;
    int c    = gid >> 5;
    int lane = gid & 31;
    if (c >= NCLASS) return;
    const float* w = weight + (size_t)c * EMB_D;
    float4 v[4];
    float s = 0.f;
    #pragma unroll
    for (int i = 0; i < 4; i++) {
        v[i] = *(const float4*)&w[lane * 4 + i * 128];
        s += v[i].x * v[i].x + v[i].y * v[i].y + v[i].z * v[i].z + v[i].w * v[i].w;
    }
    #pragma unroll
    for (int o = 16; o > 0; o >>= 1) s += __shfl_xor_sync(0xffffffffu, s, o);
    float sc = SCALE_F * rsqrtf(s);
    if (lane == 0) g_inv_norm[c] = sc;
    __half* dst = g_wh + (size_t)c * EMB_D;
    #pragma unroll
    for (int i = 0; i < 4; i++) {
        __half2 h0 = __floats2half2_rn(v[i].x * sc, v[i].y * sc);
        __half2 h1 = __floats2half2_rn(v[i].z * sc, v[i].w * sc);
        *(uint2*)&dst[lane * 4 + i * 128] = make_uint2(*(uint32_t*)&h0, *(uint32_t*)&h1);
    }
}

// ---------------------------------------------------------------------------
// Kernel 0b: embeddings fp32 -> fp16.
// ---------------------------------------------------------------------------
__global__ __launch_bounds__(256) void convert_e(const float* __restrict__ emb) {
    int i = blockIdx.x * blockDim.x + threadIdx.x;
    float4 v = *(const float4*)&emb[i * 4];
    __half2 h0 = __floats2half2_rn(v.x, v.y);
    __half2 h1 = __floats2half2_rn(v.z, v.w);
    *(uint2*)&g_eh[i * 4] = make_uint2(*(uint32_t*)&h0, *(uint32_t*)&h1);
}

// ---------------------------------------------------------------------------
// Kernel 1: fp16 mma GEMM, CTA tile 256M x 128N, warp tile 64x64 (4Mx2N),
// 4 class tiles per CTA in a flat (tile,chunk) cp.async pipeline,
// fused per-row logsumexp per tile. grid = (4, STRIPS), 256 threads.
// ---------------------------------------------------------------------------
__global__ __launch_bounds__(256, 1) void gemm_lse_h(void) {
    extern __shared__ __align__(16) char smc[];
    __half* sm    = (__half*)smc;
    float*  sm_pm = (float*)(smc + 2 * STAGE_B);       // [256][2]
    float*  sm_ps = sm_pm + 512;

    const int tid    = threadIdx.x;
    const int m_base = blockIdx.x * 256;
    const int strip  = blockIdx.y;

    const int wid  = tid >> 5, lane = tid & 31;
    const int wm   = wid & 3;                 // M warp -> rows wm*64
    const int wn   = wid >> 2;                // N warp -> cols wn*64
    const int g    = lane >> 2, tig = lane & 3;

    const uint32_t smem_base = smem_u32(sm);

    // ldmatrix per-lane byte offsets within a stage
    const uint32_t a_off = ((uint32_t)(wm * 64 + (lane & 7) + ((lane >> 3) & 1) * 8) * RS_H
                            + ((lane >> 4) & 1) * 8) * 2;
    const uint32_t b_off = (uint32_t)A_TILE_B
                         + ((uint32_t)(wn * 64 + (lane & 7) + ((lane >> 4) & 1) * 8) * RS_H
                            + ((lane >> 3) & 1) * 8) * 2;

    // flat chunk q -> (tile q>>3, kchunk q&7). 384 rows x 8 units = 3072 cp16.
    auto load_chunk = [&](int q, int stage) {
        const int tile = q >> 3;
        const int k0   = (q & 7) * 64;
        const int c0   = (strip * TILES_PER_CTA + tile) * CT;
        const uint32_t sa = smem_base + stage * STAGE_B;
        const uint32_t sb = sa + A_TILE_B;
        #pragma unroll
        for (int i = 0; i < 12; i++) {
            int id = tid + i * 256;              // 0..3071
            int r  = id >> 3;                    // 0..383
            int u  = id & 7;
            if (r < A_ROWS) {
                cp16(sa + (r * RS_H + u * 8) * 2,
                     g_eh + (size_t)(m_base + r) * EMB_D + k0 + u * 8, 16);
            } else {
                int rr = r - A_ROWS;
                int c  = c0 + rr;
                int cc = (c < NCLASS) ? c : (NCLASS - 1);
                cp16(sb + (rr * RS_H + u * 8) * 2,
                     g_wh + (size_t)cc * EMB_D + k0 + u * 8,
                     (c < NCLASS) ? 16 : 0);
            }
        }
        CP_COMMIT();
    };

    float acc[4][8][4];
    #pragma unroll
    for (int mi = 0; mi < 4; mi++)
        #pragma unroll
        for (int ni = 0; ni < 8; ni++)
            #pragma unroll
            for (int qq = 0; qq < 4; qq++) acc[mi][ni][qq] = 0.f;

    const int NCHUNK = TILES_PER_CTA * 8;
    load_chunk(0, 0);
    load_chunk(1, 1);

    #pragma unroll 1
    for (int q = 0; q < NCHUNK; q++) {
        if (q == NCHUNK - 1) { CP_WAIT(0); } else { CP_WAIT(1); }
        __syncthreads();

        const int stage = q & 1;
        const uint32_t sA = smem_base + stage * STAGE_B + a_off;
        const uint32_t sB = smem_base + stage * STAGE_B + b_off;

        #pragma unroll
        for (int ks = 0; ks < 4; ks++) {
            const uint32_t kb = (uint32_t)ks * 32;     // 16 halves
            uint32_t a[4][4];
            #pragma unroll
            for (int mi = 0; mi < 4; mi++)
                ldm_x4(a[mi], sA + (uint32_t)(mi * 16 * RS_H) * 2 + kb);
            #pragma unroll
            for (int nip = 0; nip < 4; nip++) {
                uint32_t br[4];
                ldm_x4(br, sB + (uint32_t)(nip * 16 * RS_H) * 2 + kb);
                #pragma unroll
                for (int mi = 0; mi < 4; mi++) {
                    mma_16816(acc[mi][2 * nip],     a[mi], br[0], br[1]);
                    mma_16816(acc[mi][2 * nip + 1], a[mi], br[2], br[3]);
                }
            }
        }
        __syncthreads();
        if (q + 2 < NCHUNK) load_chunk(q + 2, stage);

        // ---- tile boundary: epilogue + acc reset ----
        if ((q & 7) == 7) {
            const int tile  = q >> 3;
            const int tIdx  = strip * TILES_PER_CTA + tile;
            const int c0    = tIdx * CT;
            if (tIdx < NTILES) {
                #pragma unroll
                for (int mi = 0; mi < 4; mi++) {
                    #pragma unroll
                    for (int half = 0; half < 2; half++) {
                        const int row = wm * 64 + mi * 16 + half * 8 + g;
                        float lv[16];
                        float mx = -FLT_MAX;
                        #pragma unroll
                        for (int ni = 0; ni < 8; ni++) {
                            int col = wn * 64 + ni * 8 + 2 * tig;
                            float v0 = acc[mi][ni][half * 2 + 0];
                            float v1 = acc[mi][ni][half * 2 + 1];
                            if (c0 + col     >= NCLASS) v0 = -FLT_MAX;
                            if (c0 + col + 1 >= NCLASS) v1 = -FLT_MAX;
                            lv[ni * 2]     = v0;
                            lv[ni * 2 + 1] = v1;
                            mx = fmaxf(mx, fmaxf(v0, v1));
                        }
                        float ss = 0.f;
                        #pragma unroll
                        for (int j = 0; j < 16; j++) ss += __expf(lv[j] - mx);
                        #pragma unroll
                        for (int d = 1; d <= 2; d <<= 1) {
                            float om = __shfl_xor_sync(0xffffffffu, mx, d);
                            float os = __shfl_xor_sync(0xffffffffu, ss, d);
                            float nm = fmaxf(mx, om);
                            ss = ss * __expf(mx - nm) + os * __expf(om - nm);
                            mx = nm;
                        }
                        if (tig == 0) {
                            sm_pm[row * 2 + wn] = mx;
                            sm_ps[row * 2 + wn] = ss;
                        }
                    }
                }
                __syncthreads();
                {
                    float m0 = sm_pm[tid * 2], m1 = sm_pm[tid * 2 + 1];
                    float s0 = sm_ps[tid * 2], s1 = sm_ps[tid * 2 + 1];
                    float M = fmaxf(m0, m1);
                    float S = s0 * __expf(m0 - M) + s1 * __expf(m1 - M);
                    g_m[(size_t)(m_base + tid) * NTILES + tIdx] = M;
                    g_s[(size_t)(m_base + tid) * NTILES + tIdx] = S;
                }
                __syncthreads();
            }
            #pragma unroll
            for (int mi = 0; mi < 4; mi++)
                #pragma unroll
                for (int ni = 0; ni < 8; ni++)
                    #pragma unroll
                    for (int qq = 0; qq < 4; qq++) acc[mi][ni][qq] = 0.f;
        }
    }
}

// ---------------------------------------------------------------------------
// Kernel 3: combine tile partials + exact label cosine + ArcFace correction.
// One block per batch row; label dot product fused in (fp32 exact).
// ---------------------------------------------------------------------------
__global__ __launch_bounds__(256) void finalize_rows_kernel(const float* __restrict__ emb,
                                                            const void* __restrict__ labels,
                                                            const float* __restrict__ weight) {
    const int b   = blockIdx.x;
    const int tid = threadIdx.x;
    __shared__ float sh[256];

    long long lab;
    if (g_lab_is64) lab = ((const long long*)labels)[b];
    else            lab = (long long)((const int*)labels)[b];
    if (lab < 0) lab = 0;
    if (lab >= NCLASS) lab = NCLASS - 1;

    // exact fp32 label dot: 512 elems, 2 per thread
    {
        float2 ev = *(const float2*)&emb[(size_t)b * EMB_D + tid * 2];
        float2 wv = *(const float2*)&weight[(size_t)lab * EMB_D + tid * 2];
        sh[tid] = ev.x * wv.x + ev.y * wv.y;
    }
    __syncthreads();
    for (int o = 128; o > 0; o >>= 1) {
        if (tid < o) sh[tid] += sh[tid + o];
        __syncthreads();
    }
    float dot = sh[0];
    __syncthreads();

    float mx = -FLT_MAX;
    for (int t = tid; t < NTILES; t += 256)
        mx = fmaxf(mx, g_m[(size_t)b * NTILES + t]);
    sh[tid] = mx;
    __syncthreads();
    for (int o = 128; o > 0; o >>= 1) {
        if (tid < o) sh[tid] = fmaxf(sh[tid], sh[tid + o]);
        __syncthreads();
    }
    float M = sh[0];
    __syncthreads();

    float s = 0.f;
    for (int t = tid; t < NTILES; t += 256)
        s += g_s[(size_t)b * NTILES + t] * __expf(g_m[(size_t)b * NTILES + t] - M);
    sh[tid] = s;
    __syncthreads();
    for (int o = 128; o > 0; o >>= 1) {
        if (tid < o) sh[tid] += sh[tid + o];
        __syncthreads();
    }

    if (tid == 0) {
        float S  = sh[0];
        float cv = dot * g_inv_norm[lab] * (1.0f / SCALE_F);   // cosine
        float l_cos = SCALE_F * cv;
        float sine  = sqrtf(fmaxf(0.f, fminf(1.f, 1.f - cv * cv)));
        float phi   = cv * COS_M - sine * SIN_M;
        if (!(cv > TH_C)) phi = cv - MM_C;
        float l_phi = SCALE_F * phi;
        float Sc = S - expf(l_cos - M) + expf(l_phi - M);
        g_nll[b] = M + logf(Sc) - l_phi;
    }
}

// ---------------------------------------------------------------------------
// Kernel 4: mean -> scalar.
// ---------------------------------------------------------------------------
__global__ __launch_bounds__(256) void mean_kernel(float* __restrict__ out) {
    const int tid = threadIdx.x;
    __shared__ float sh[256];
    float s = 0.f;
    for (int i = tid; i < B_ROWS; i += 256) s += g_nll[i];
    sh[tid] = s;
    __syncthreads();
    for (int o = 128; o > 0; o >>= 1) {
        if (tid < o) sh[tid] += sh[tid + o];
        __syncthreads();
    }
    if (tid == 0) out[0] = sh[0] * (1.0f / (float)B_ROWS);
}

// ---------------------------------------------------------------------------
extern "C" void kernel_launch(void* const* d_in, const int* in_sizes, int n_in,
                              void* d_out, int out_size) {
    const float* emb    = (const float*)d_in[0];
    const void*  labels = d_in[1];
    const float* weight = (const float*)d_in[2];
    float*       out    = (float*)d_out;

    cudaFuncSetAttribute(gemm_lse_h, cudaFuncAttributeMaxDynamicSharedMemorySize, SMEM_DYN);

    detect_labels_kernel<<<1, 512>>>(labels);
    norm_convert_w<<<(NCLASS + 7) / 8, 256>>>(weight);
    convert_e<<<B_ROWS * EMB_D / 4 / 256, 256>>>(emb);

    dim3 grid(4, STRIPS);
    gemm_lse_h<<<grid, 256, SMEM_DYN>>>();

    finalize_rows_kernel<<<B_ROWS, 256>>>(emb, labels, weight);
    mean_kernel<<<1, 256>>>(out);
}

// round 10
// speedup vs baseline: 1.0942x; 1.0942x over previous
#include <cuda_runtime.h>
#include <cuda_fp16.h>
#include <math.h>
#include <float.h>
#include <stdint.h>

// ---------------- problem constants ----------------
#define B_ROWS   1024
#define EMB_D    512
#define NCLASS   100000
#define CT       128                              // class tile (N)
#define NTILES   ((NCLASS + CT - 1) / CT)         // 782
#define SCALE_F  30.0f

#define TILES_PER_CTA 8
#define STRIPS   98                               // 98*8 = 784 >= 782

// ArcFace margin constants (margin = 0.3)
#define COS_M 0.9553364891256061f
#define SIN_M 0.2955202066613396f
#define TH_C  (-0.9553364891256061f)
#define MM_C  0.08865606199840186f

// ---------------- scratch ----------------
__device__ __half g_wh[(size_t)NCLASS * EMB_D];   // fp16 weight, 30/||w|| folded
__device__ __half g_eh[B_ROWS * EMB_D];           // fp16 embeddings
__device__ float  g_inv_norm[NCLASS];             // 30/||w|| (exact label path)
__device__ float  g_m[B_ROWS * NTILES];
__device__ float  g_s[B_ROWS * NTILES];
__device__ float  g_nll[B_ROWS];
__device__ int    g_lab_is64;

// ---------------- helpers ----------------
__device__ __forceinline__ uint32_t smem_u32(const void* p) {
    uint32_t a;
    asm("{ .reg .u64 t; cvta.to.shared.u64 t, %1; cvt.u32.u64 %0, t; }" : "=r"(a) : "l"(p));
    return a;
}
__device__ __forceinline__ void cp16(uint32_t dst, const void* src, int bytes) {
    asm volatile("cp.async.cg.shared.global [%0], [%1], 16, %2;" :: "r"(dst), "l"(src), "r"(bytes));
}
#define CP_COMMIT()  asm volatile("cp.async.commit_group;" ::: "memory")
#define CP_WAIT(n)   asm volatile("cp.async.wait_group %0;" :: "n"(n) : "memory")

__device__ __forceinline__ void mma_16816(float* c, const uint32_t* a, uint32_t b0, uint32_t b1) {
    asm volatile(
        "mma.sync.aligned.m16n8k16.row.col.f32.f16.f16.f32 "
        "{%0,%1,%2,%3}, {%4,%5,%6,%7}, {%8,%9}, {%0,%1,%2,%3};"
        : "+f"(c[0]), "+f"(c[1]), "+f"(c[2]), "+f"(c[3])
        : "r"(a[0]), "r"(a[1]), "r"(a[2]), "r"(a[3]), "r"(b0), "r"(b1));
}
__device__ __forceinline__ void ldm_x4(uint32_t* r, uint32_t addr) {
    asm volatile("ldmatrix.sync.aligned.m8n8.x4.shared.b16 {%0,%1,%2,%3}, [%4];"
                 : "=r"(r[0]), "=r"(r[1]), "=r"(r[2]), "=r"(r[3]) : "r"(addr));
}

// smem geometry: fp16, K-chunk 64, padded row stride 72 halves (144 B)
#define RS_H        72
#define CHUNK_B     (128 * RS_H * 2)               // 18432 B (128 rows x 64 k)
#define A_BYTES     (8 * CHUNK_B)                  // A resident: all 8 K-chunks
#define NBSTAGE     3
#define PART_OFF    (A_BYTES + NBSTAGE * CHUNK_B)  // 202752
#define SMEM_DYN    (PART_OFF + 2048)              // 204800 B

// ---------------------------------------------------------------------------
// Kernel A: probe labels dtype (int64 vs int32 under JAX x64-off).
// ---------------------------------------------------------------------------
__global__ __launch_bounds__(512) void detect_labels_kernel(const void* __restrict__ labels) {
    __shared__ int bad;
    if (threadIdx.x == 0) bad = 0;
    __syncthreads();
    long long v = ((const long long*)labels)[threadIdx.x];
    if (v < 0 || v >= NCLASS) atomicOr(&bad, 1);
    __syncthreads();
    if (threadIdx.x == 0) g_lab_is64 = bad ? 0 : 1;
}

// ---------------------------------------------------------------------------
// Kernel 0: fused per-class norm + fp16 convert (30/||w|| folded).
// ---------------------------------------------------------------------------
__global__ __launch_bounds__(256) void norm_convert_w(const float* __restrict__ weight) {
    int gid  = blockIdx.x * blockDim.x + threadIdx.x;
    int c    = gid >> 5;
    int lane = gid & 31;
    if (c >= NCLASS) return;
    const float* w = weight + (size_t)c * EMB_D;
    float4 v[4];
    float s = 0.f;
    #pragma unroll
    for (int i = 0; i < 4; i++) {
        v[i] = *(const float4*)&w[lane * 4 + i * 128];
        s += v[i].x * v[i].x + v[i].y * v[i].y + v[i].z * v[i].z + v[i].w * v[i].w;
    }
    #pragma unroll
    for (int o = 16; o > 0; o >>= 1) s += __shfl_xor_sync(0xffffffffu, s, o);
    float sc = SCALE_F * rsqrtf(s);
    if (lane == 0) g_inv_norm[c] = sc;
    __half* dst = g_wh + (size_t)c * EMB_D;
    #pragma unroll
    for (int i = 0; i < 4; i++) {
        __half2 h0 = __floats2half2_rn(v[i].x * sc, v[i].y * sc);
        __half2 h1 = __floats2half2_rn(v[i].z * sc, v[i].w * sc);
        *(uint2*)&dst[lane * 4 + i * 128] = make_uint2(*(uint32_t*)&h0, *(uint32_t*)&h1);
    }
}

// ---------------------------------------------------------------------------
// Kernel 0b: embeddings fp32 -> fp16.
// ---------------------------------------------------------------------------
__global__ __launch_bounds__(256) void convert_e(const float* __restrict__ emb) {
    int i = blockIdx.x * blockDim.x + threadIdx.x;
    float4 v = *(const float4*)&emb[i * 4];
    __half2 h0 = __floats2half2_rn(v.x, v.y);
    __half2 h1 = __floats2half2_rn(v.z, v.w);
    *(uint2*)&g_eh[i * 4] = make_uint2(*(uint32_t*)&h0, *(uint32_t*)&h1);
}

// ---------------------------------------------------------------------------
// Kernel 1: A-resident fp16 mma GEMM + fused logsumexp.
// CTA: 128M x 128N, warp tile 32x64 (4Mx2N), A (128x512 fp16 = 144KB padded)
// loaded once; B streamed through a 3-stage ring (1 sync per chunk).
// 8 class tiles per CTA. grid = (8, STRIPS), 256 threads, 1 CTA/SM.
// ---------------------------------------------------------------------------
__global__ __launch_bounds__(256, 1) void gemm_lse_h(void) {
    extern __shared__ __align__(16) char smc[];
    float*  sm_pm = (float*)(smc + PART_OFF);          // [128][2]
    float*  sm_ps = sm_pm + 256;

    const int tid    = threadIdx.x;
    const int m_base = blockIdx.x * 128;
    const int strip  = blockIdx.y;

    const int wid  = tid >> 5, lane = tid & 31;
    const int wm   = wid & 3;                 // M warp -> rows wm*32
    const int wn   = wid >> 2;                // N warp -> cols wn*64
    const int g    = lane >> 2, tig = lane & 3;

    const uint32_t smem_base = smem_u32(smc);

    // ldmatrix per-lane byte offsets (within one 128-row chunk)
    const uint32_t a_off = ((uint32_t)(wm * 32 + (lane & 7) + ((lane >> 3) & 1) * 8) * RS_H
                            + ((lane >> 4) & 1) * 8) * 2;
    const uint32_t b_off = ((uint32_t)(wn * 64 + (lane & 7) + ((lane >> 4) & 1) * 8) * RS_H
                            + ((lane >> 3) & 1) * 8) * 2;

    // ---- load resident A: 8 chunks x 1024 cp16 = 32 per thread ----
    {
        #pragma unroll
        for (int i = 0; i < 32; i++) {
            int id = tid + i * 256;                  // 0..8191
            int ck = id >> 10;                       // K chunk 0..7
            int rr = (id >> 3) & 127;                // row
            int u  = id & 7;                         // 16B unit
            cp16(smem_base + ck * CHUNK_B + (rr * RS_H + u * 8) * 2,
                 g_eh + (size_t)(m_base + rr) * EMB_D + ck * 64 + u * 8, 16);
        }
        CP_COMMIT();
    }

    // ---- B chunk loader: flat q -> (tile q>>3, kchunk q&7), 4 cp16/thread ----
    auto load_b = [&](int q, int stage) {
        const int tile = q >> 3;
        const int k0   = (q & 7) * 64;
        const int c0   = (strip * TILES_PER_CTA + tile) * CT;
        const uint32_t sb = smem_base + A_BYTES + stage * CHUNK_B;
        #pragma unroll
        for (int i = 0; i < 4; i++) {
            int id = tid + i * 256;                  // 0..1023
            int rr = id >> 3;
            int u  = id & 7;
            int c  = c0 + rr;
            int cc = (c < NCLASS) ? c : (NCLASS - 1);
            cp16(sb + (rr * RS_H + u * 8) * 2,
                 g_wh + (size_t)cc * EMB_D + k0 + u * 8,
                 (c < NCLASS) ? 16 : 0);
        }
        CP_COMMIT();
    };

    float acc[2][8][4];
    #pragma unroll
    for (int mi = 0; mi < 2; mi++)
        #pragma unroll
        for (int ni = 0; ni < 8; ni++)
            #pragma unroll
            for (int qq = 0; qq < 4; qq++) acc[mi][ni][qq] = 0.f;

    const int NQ = TILES_PER_CTA * 8;                // 64
    load_b(0, 0);
    load_b(1, 1);
    // pending groups: {A, B0, B1}

    int stage = 2;                                    // ring pointer for q+2

    #pragma unroll 1
    for (int q = 0; q < NQ; q++) {
        if (q >= NQ - 1) { CP_WAIT(0); } else { CP_WAIT(1); }   // chunk q (and A) ready
        __syncthreads();

        const int bstage = (q < 2) ? q : ((q - 2 + 2) % NBSTAGE + 0);  // see ring below
        // ring: chunk q lives in stage (q % 3) because loads go 0,1,2,0,1,2,...
        const uint32_t sA = smem_base + (uint32_t)(q & 7) * CHUNK_B + a_off;
        const uint32_t sB = smem_base + A_BYTES + (uint32_t)(q % NBSTAGE) * CHUNK_B + b_off;
        (void)bstage;

        #pragma unroll
        for (int ks = 0; ks < 4; ks++) {
            const uint32_t kb = (uint32_t)ks * 32;     // 16 halves
            uint32_t a[2][4];
            ldm_x4(a[0], sA + kb);
            ldm_x4(a[1], sA + (16 * RS_H) * 2 + kb);
            #pragma unroll
            for (int nip = 0; nip < 4; nip++) {
                uint32_t br[4];
                ldm_x4(br, sB + (uint32_t)(nip * 16 * RS_H) * 2 + kb);
                mma_16816(acc[0][2 * nip],     a[0], br[0], br[1]);
                mma_16816(acc[1][2 * nip],     a[1], br[0], br[1]);
                mma_16816(acc[0][2 * nip + 1], a[0], br[2], br[3]);
                mma_16816(acc[1][2 * nip + 1], a[1], br[2], br[3]);
            }
        }
        // prefetch chunk q+2 into stage (q+2)%3 — that buffer held chunk q-1,
        // already consumed last iteration; current readers use stage q%3.
        if (q + 2 < NQ) { load_b(q + 2, (q + 2) % NBSTAGE); }
        (void)stage;

        // ---- tile boundary: epilogue + acc reset ----
        if ((q & 7) == 7) {
            const int tile = q >> 3;
            const int tIdx = strip * TILES_PER_CTA + tile;
            const int c0   = tIdx * CT;
            if (tIdx < NTILES) {
                __syncthreads();                      // sm_pm reuse safety
                #pragma unroll
                for (int mi = 0; mi < 2; mi++) {
                    #pragma unroll
                    for (int half = 0; half < 2; half++) {
                        const int row = wm * 32 + mi * 16 + half * 8 + g;
                        float lv[16];
                        float mx = -FLT_MAX;
                        #pragma unroll
                        for (int ni = 0; ni < 8; ni++) {
                            int col = wn * 64 + ni * 8 + 2 * tig;
                            float v0 = acc[mi][ni][half * 2 + 0];
                            float v1 = acc[mi][ni][half * 2 + 1];
                            if (c0 + col     >= NCLASS) v0 = -FLT_MAX;
                            if (c0 + col + 1 >= NCLASS) v1 = -FLT_MAX;
                            lv[ni * 2]     = v0;
                            lv[ni * 2 + 1] = v1;
                            mx = fmaxf(mx, fmaxf(v0, v1));
                        }
                        float ss = 0.f;
                        #pragma unroll
                        for (int j = 0; j < 16; j++) ss += __expf(lv[j] - mx);
                        #pragma unroll
                        for (int d = 1; d <= 2; d <<= 1) {
                            float om = __shfl_xor_sync(0xffffffffu, mx, d);
                            float os = __shfl_xor_sync(0xffffffffu, ss, d);
                            float nm = fmaxf(mx, om);
                            ss = ss * __expf(mx - nm) + os * __expf(om - nm);
                            mx = nm;
                        }
                        if (tig == 0) {
                            sm_pm[row * 2 + wn] = mx;
                            sm_ps[row * 2 + wn] = ss;
                        }
                    }
                }
                __syncthreads();
                if (tid < 128) {
                    float m0 = sm_pm[tid * 2], m1 = sm_pm[tid * 2 + 1];
                    float s0 = sm_ps[tid * 2], s1 = sm_ps[tid * 2 + 1];
                    float M = fmaxf(m0, m1);
                    float S = s0 * __expf(m0 - M) + s1 * __expf(m1 - M);
                    g_m[(size_t)(m_base + tid) * NTILES + tIdx] = M;
                    g_s[(size_t)(m_base + tid) * NTILES + tIdx] = S;
                }
            }
            #pragma unroll
            for (int mi = 0; mi < 2; mi++)
                #pragma unroll
                for (int ni = 0; ni < 8; ni++)
                    #pragma unroll
                    for (int qq = 0; qq < 4; qq++) acc[mi][ni][qq] = 0.f;
        }
    }
}

// ---------------------------------------------------------------------------
// Kernel 3: combine tile partials + exact label cosine + ArcFace correction.
// ---------------------------------------------------------------------------
__global__ __launch_bounds__(256) void finalize_rows_kernel(const float* __restrict__ emb,
                                                            const void* __restrict__ labels,
                                                            const float* __restrict__ weight) {
    const int b   = blockIdx.x;
    const int tid = threadIdx.x;
    __shared__ float sh[256];

    long long lab;
    if (g_lab_is64) lab = ((const long long*)labels)[b];
    else            lab = (long long)((const int*)labels)[b];
    if (lab < 0) lab = 0;
    if (lab >= NCLASS) lab = NCLASS - 1;

    {
        float2 ev = *(const float2*)&emb[(size_t)b * EMB_D + tid * 2];
        float2 wv = *(const float2*)&weight[(size_t)lab * EMB_D + tid * 2];
        sh[tid] = ev.x * wv.x + ev.y * wv.y;
    }
    __syncthreads();
    for (int o = 128; o > 0; o >>= 1) {
        if (tid < o) sh[tid] += sh[tid + o];
        __syncthreads();
    }
    float dot = sh[0];
    __syncthreads();

    float mx = -FLT_MAX;
    for (int t = tid; t < NTILES; t += 256)
        mx = fmaxf(mx, g_m[(size_t)b * NTILES + t]);
    sh[tid] = mx;
    __syncthreads();
    for (int o = 128; o > 0; o >>= 1) {
        if (tid < o) sh[tid] = fmaxf(sh[tid], sh[tid + o]);
        __syncthreads();
    }
    float M = sh[0];
    __syncthreads();

    float s = 0.f;
    for (int t = tid; t < NTILES; t += 256)
        s += g_s[(size_t)b * NTILES + t] * __expf(g_m[(size_t)b * NTILES + t] - M);
    sh[tid] = s;
    __syncthreads();
    for (int o = 128; o > 0; o >>= 1) {
        if (tid < o) sh[tid] += sh[tid + o];
        __syncthreads();
    }

    if (tid == 0) {
        float S  = sh[0];
        float cv = dot * g_inv_norm[lab] * (1.0f / SCALE_F);
        float l_cos = SCALE_F * cv;
        float sine  = sqrtf(fmaxf(0.f, fminf(1.f, 1.f - cv * cv)));
        float phi   = cv * COS_M - sine * SIN_M;
        if (!(cv > TH_C)) phi = cv - MM_C;
        float l_phi = SCALE_F * phi;
        float Sc = S - expf(l_cos - M) + expf(l_phi - M);
        g_nll[b] = M + logf(Sc) - l_phi;
    }
}

// ---------------------------------------------------------------------------
// Kernel 4: mean -> scalar.
// ---------------------------------------------------------------------------
__global__ __launch_bounds__(256) void mean_kernel(float* __restrict__ out) {
    const int tid = threadIdx.x;
    __shared__ float sh[256];
    float s = 0.f;
    for (int i = tid; i < B_ROWS; i += 256) s += g_nll[i];
    sh[tid] = s;
    __syncthreads();
    for (int o = 128; o > 0; o >>= 1) {
        if (tid < o) sh[tid] += sh[tid + o];
        __syncthreads();
    }
    if (tid == 0) out[0] = sh[0] * (1.0f / (float)B_ROWS);
}

// ---------------------------------------------------------------------------
extern "C" void kernel_launch(void* const* d_in, const int* in_sizes, int n_in,
                              void* d_out, int out_size) {
    const float* emb    = (const float*)d_in[0];
    const void*  labels = d_in[1];
    const float* weight = (const float*)d_in[2];
    float*       out    = (float*)d_out;

    cudaFuncSetAttribute(gemm_lse_h, cudaFuncAttributeMaxDynamicSharedMemorySize, SMEM_DYN);

    detect_labels_kernel<<<1, 512>>>(labels);
    norm_convert_w<<<(NCLASS + 7) / 8, 256>>>(weight);
    convert_e<<<B_ROWS * EMB_D / 4 / 256, 256>>>(emb);

    dim3 grid(8, STRIPS);
    gemm_lse_h<<<grid, 256, SMEM_DYN>>>();

    finalize_rows_kernel<<<B_ROWS, 256>>>(emb, labels, weight);
    mean_kernel<<<1, 256>>>(out);
}

// round 11
// speedup vs baseline: 1.2389x; 1.1322x over previous
#include <cuda_runtime.h>
#include <cuda_fp16.h>
#include <math.h>
#include <float.h>
#include <stdint.h>

// ---------------- problem constants ----------------
#define B_ROWS   1024
#define EMB_D    512
#define NCLASS   100000
#define CT       128                              // class tile (N)
#define NTILES   ((NCLASS + CT - 1) / CT)         // 782
#define NPAIRS   (NTILES / 2)                     // 391
#define SCALE_F  30.0f

// ArcFace margin constants (margin = 0.3)
#define COS_M 0.9553364891256061f
#define SIN_M 0.2955202066613396f
#define TH_C  (-0.9553364891256061f)
#define MM_C  0.08865606199840186f

// ---------------- scratch ----------------
__device__ __half g_wh[(size_t)NCLASS * EMB_D];   // fp16 weight, 30/||w|| folded
__device__ __half g_eh[B_ROWS * EMB_D];           // fp16 embeddings
__device__ float  g_inv_norm[NCLASS];             // 30/||w|| (exact label path)
__device__ float  g_m[B_ROWS * NTILES];
__device__ float  g_s[B_ROWS * NTILES];
__device__ float  g_nll[B_ROWS];
__device__ int    g_lab_is64;

// ---------------- helpers ----------------
__device__ __forceinline__ uint32_t smem_u32(const void* p) {
    uint32_t a;
    asm("{ .reg .u64 t; cvta.to.shared.u64 t, %1; cvt.u32.u64 %0, t; }" : "=r"(a) : "l"(p));
    return a;
}
__device__ __forceinline__ void cp16(uint32_t dst, const void* src, int bytes) {
    asm volatile("cp.async.cg.shared.global [%0], [%1], 16, %2;" :: "r"(dst), "l"(src), "r"(bytes));
}
#define CP_COMMIT()  asm volatile("cp.async.commit_group;" ::: "memory")
#define CP_WAIT(n)   asm volatile("cp.async.wait_group %0;" :: "n"(n) : "memory")

__device__ __forceinline__ void mma_16816(float* c, const uint32_t* a, uint32_t b0, uint32_t b1) {
    asm volatile(
        "mma.sync.aligned.m16n8k16.row.col.f32.f16.f16.f32 "
        "{%0,%1,%2,%3}, {%4,%5,%6,%7}, {%8,%9}, {%0,%1,%2,%3};"
        : "+f"(c[0]), "+f"(c[1]), "+f"(c[2]), "+f"(c[3])
        : "r"(a[0]), "r"(a[1]), "r"(a[2]), "r"(a[3]), "r"(b0), "r"(b1));
}
__device__ __forceinline__ void ldm_x4(uint32_t* r, uint32_t addr) {
    asm volatile("ldmatrix.sync.aligned.m8n8.x4.shared.b16 {%0,%1,%2,%3}, [%4];"
                 : "=r"(r[0]), "=r"(r[1]), "=r"(r[2]), "=r"(r[3]) : "r"(addr));
}

// smem geometry: fp16, K-chunk 64, padded row stride 72 halves (144 B)
// stage = A(128 rows) + B(256 rows), 3-stage ring
#define RS_H        72
#define A_ROWS_T    128
#define B_ROWS_T    256
#define A_PART_B    (A_ROWS_T * RS_H * 2)          // 18432
#define STAGE_B     ((A_ROWS_T + B_ROWS_T) * RS_H * 2)   // 55296
#define NSTAGE      3
#define PART_OFF    (NSTAGE * STAGE_B)             // 165888
#define SMEM_DYN    (PART_OFF + 4096)              // 169984

// ---------------------------------------------------------------------------
// Kernel A: probe labels dtype (int64 vs int32 under JAX x64-off).
// ---------------------------------------------------------------------------
__global__ __launch_bounds__(512) void detect_labels_kernel(const void* __restrict__ labels) {
    __shared__ int bad;
    if (threadIdx.x == 0) bad = 0;
    __syncthreads();
    long long v = ((const long long*)labels)[threadIdx.x];
    if (v < 0 || v >= NCLASS) atomicOr(&bad, 1);
    __syncthreads();
    if (threadIdx.x == 0) g_lab_is64 = bad ? 0 : 1;
}

// ---------------------------------------------------------------------------
// Kernel 0: fused per-class norm + fp16 convert (30/||w|| folded).
// ---------------------------------------------------------------------------
__global__ __launch_bounds__(256) void norm_convert_w(const float* __restrict__ weight) {
    int gid  = blockIdx.x * blockDim.x + threadIdx.x;
    int c    = gid >> 5;
    int lane = gid & 31;
    if (c >= NCLASS) return;
    const float* w = weight + (size_t)c * EMB_D;
    float4 v[4];
    float s = 0.f;
    #pragma unroll
    for (int i = 0; i < 4; i++) {
        v[i] = *(const float4*)&w[lane * 4 + i * 128];
        s += v[i].x * v[i].x + v[i].y * v[i].y + v[i].z * v[i].z + v[i].w * v[i].w;
    }
    #pragma unroll
    for (int o = 16; o > 0; o >>= 1) s += __shfl_xor_sync(0xffffffffu, s, o);
    float sc = SCALE_F * rsqrtf(s);
    if (lane == 0) g_inv_norm[c] = sc;
    __half* dst = g_wh + (size_t)c * EMB_D;
    #pragma unroll
    for (int i = 0; i < 4; i++) {
        __half2 h0 = __floats2half2_rn(v[i].x * sc, v[i].y * sc);
        __half2 h1 = __floats2half2_rn(v[i].z * sc, v[i].w * sc);
        *(uint2*)&dst[lane * 4 + i * 128] = make_uint2(*(uint32_t*)&h0, *(uint32_t*)&h1);
    }
}

// ---------------------------------------------------------------------------
// Kernel 0b: embeddings fp32 -> fp16.
// ---------------------------------------------------------------------------
__global__ __launch_bounds__(256) void convert_e(const float* __restrict__ emb) {
    int i = blockIdx.x * blockDim.x + threadIdx.x;
    float4 v = *(const float4*)&emb[i * 4];
    __half2 h0 = __floats2half2_rn(v.x, v.y);
    __half2 h1 = __floats2half2_rn(v.z, v.w);
    *(uint2*)&g_eh[i * 4] = make_uint2(*(uint32_t*)&h0, *(uint32_t*)&h1);
}

// ---------------------------------------------------------------------------
// Kernel 1: fp16 mma GEMM, CTA tile 128M x 256N (a class-tile PAIR),
// 16 warps = 4(M) x 4(N), warp tile 32x64, 3-stage ring, 1 sync per chunk,
// fused per-row logsumexp for both tiles. grid = (8, NPAIRS), 512 threads.
// ---------------------------------------------------------------------------
__global__ __launch_bounds__(512, 1) void gemm_lse_h(void) {
    extern __shared__ __align__(16) char smc[];
    float*  sm_pm = (float*)(smc + PART_OFF);          // [128][4]
    float*  sm_ps = sm_pm + 512;

    const int tid    = threadIdx.x;
    const int m_base = blockIdx.x * 128;
    const int c0     = blockIdx.y * 256;               // pair base class

    const int wid  = tid >> 5, lane = tid & 31;
    const int wm   = wid & 3;                 // M warp -> rows wm*32
    const int wn   = wid >> 2;                // N warp -> cols wn*64 (0..3)
    const int g    = lane >> 2, tig = lane & 3;

    const uint32_t smem_base = smem_u32(smc);

    // ldmatrix per-lane byte offsets within a stage
    const uint32_t a_off = ((uint32_t)(wm * 32 + (lane & 7) + ((lane >> 3) & 1) * 8) * RS_H
                            + ((lane >> 4) & 1) * 8) * 2;
    const uint32_t b_off = (uint32_t)A_PART_B
                         + ((uint32_t)(wn * 64 + (lane & 7) + ((lane >> 4) & 1) * 8) * RS_H
                            + ((lane >> 3) & 1) * 8) * 2;

    // stage fill: A 128 rows + B 256 rows, 8 x 16B units each = 3072 cp16,
    // 512 threads -> 6 per thread.
    auto load_stage = [&](int kt, int stage) {
        const int k0 = kt * 64;
        const uint32_t sa = smem_base + stage * STAGE_B;
        const uint32_t sb = sa + A_PART_B;
        #pragma unroll
        for (int i = 0; i < 6; i++) {
            int id = tid + i * 512;              // 0..3071
            int r  = id >> 3;                    // 0..383
            int u  = id & 7;
            if (r < A_ROWS_T) {
                cp16(sa + (r * RS_H + u * 8) * 2,
                     g_eh + (size_t)(m_base + r) * EMB_D + k0 + u * 8, 16);
            } else {
                int rr = r - A_ROWS_T;
                int c  = c0 + rr;
                int cc = (c < NCLASS) ? c : (NCLASS - 1);
                cp16(sb + (rr * RS_H + u * 8) * 2,
                     g_wh + (size_t)cc * EMB_D + k0 + u * 8,
                     (c < NCLASS) ? 16 : 0);
            }
        }
        CP_COMMIT();
    };

    float acc[2][8][4];
    #pragma unroll
    for (int mi = 0; mi < 2; mi++)
        #pragma unroll
        for (int ni = 0; ni < 8; ni++)
            #pragma unroll
            for (int qq = 0; qq < 4; qq++) acc[mi][ni][qq] = 0.f;

    load_stage(0, 0);
    load_stage(1, 1);

    #pragma unroll 1
    for (int kt = 0; kt < 8; kt++) {
        if (kt == 7) { CP_WAIT(0); } else { CP_WAIT(1); }
        __syncthreads();
        // prefetch kt+2 into ring slot (kt+2)%3 — that buffer held chunk kt-1,
        // fully consumed before this barrier (ldmatrix is synchronous).
        if (kt + 2 < 8) load_stage(kt + 2, (kt + 2) % NSTAGE);

        const uint32_t sA = smem_base + (uint32_t)(kt % NSTAGE) * STAGE_B + a_off;
        const uint32_t sB = smem_base + (uint32_t)(kt % NSTAGE) * STAGE_B + b_off;

        #pragma unroll
        for (int ks = 0; ks < 4; ks++) {
            const uint32_t kb = (uint32_t)ks * 32;     // 16 halves
            uint32_t a[2][4];
            ldm_x4(a[0], sA + kb);
            ldm_x4(a[1], sA + (16 * RS_H) * 2 + kb);
            #pragma unroll
            for (int nip = 0; nip < 4; nip++) {
                uint32_t br[4];
                ldm_x4(br, sB + (uint32_t)(nip * 16 * RS_H) * 2 + kb);
                mma_16816(acc[0][2 * nip],     a[0], br[0], br[1]);
                mma_16816(acc[1][2 * nip],     a[1], br[0], br[1]);
                mma_16816(acc[0][2 * nip + 1], a[0], br[2], br[3]);
                mma_16816(acc[1][2 * nip + 1], a[1], br[2], br[3]);
            }
        }
    }

    // ---- epilogue: per-row (max, sumexp) per 64-col warp slice ----
    #pragma unroll
    for (int mi = 0; mi < 2; mi++) {
        #pragma unroll
        for (int half = 0; half < 2; half++) {
            const int row = wm * 32 + mi * 16 + half * 8 + g;
            float lv[16];
            float mx = -FLT_MAX;
            #pragma unroll
            for (int ni = 0; ni < 8; ni++) {
                int col = wn * 64 + ni * 8 + 2 * tig;       // 0..255
                float v0 = acc[mi][ni][half * 2 + 0];
                float v1 = acc[mi][ni][half * 2 + 1];
                if (c0 + col     >= NCLASS) v0 = -FLT_MAX;
                if (c0 + col + 1 >= NCLASS) v1 = -FLT_MAX;
                lv[ni * 2]     = v0;
                lv[ni * 2 + 1] = v1;
                mx = fmaxf(mx, fmaxf(v0, v1));
            }
            float ss = 0.f;
            #pragma unroll
            for (int j = 0; j < 16; j++) ss += __expf(lv[j] - mx);
            #pragma unroll
            for (int d = 1; d <= 2; d <<= 1) {
                float om = __shfl_xor_sync(0xffffffffu, mx, d);
                float os = __shfl_xor_sync(0xffffffffu, ss, d);
                float nm = fmaxf(mx, om);
                ss = ss * __expf(mx - nm) + os * __expf(om - nm);
                mx = nm;
            }
            if (tig == 0) {
                sm_pm[row * 4 + wn] = mx;
                sm_ps[row * 4 + wn] = ss;
            }
        }
    }
    __syncthreads();

    // combine warp slices: wn {0,1} -> tile pair 0, {2,3} -> pair 1
    if (tid < 256) {
        const int row  = tid & 127;
        const int pair = tid >> 7;                 // 0/1
        float m0 = sm_pm[row * 4 + 2 * pair], m1 = sm_pm[row * 4 + 2 * pair + 1];
        float s0 = sm_ps[row * 4 + 2 * pair], s1 = sm_ps[row * 4 + 2 * pair + 1];
        float M = fmaxf(m0, m1);
        float S = s0 * __expf(m0 - M) + s1 * __expf(m1 - M);
        const int tIdx = blockIdx.y * 2 + pair;    // < NTILES (782 even)
        g_m[(size_t)(m_base + row) * NTILES + tIdx] = M;
        g_s[(size_t)(m_base + row) * NTILES + tIdx] = S;
    }
}

// ---------------------------------------------------------------------------
// Kernel 3: combine tile partials + exact label cosine + ArcFace correction.
// ---------------------------------------------------------------------------
__global__ __launch_bounds__(256) void finalize_rows_kernel(const float* __restrict__ emb,
                                                            const void* __restrict__ labels,
                                                            const float* __restrict__ weight) {
    const int b   = blockIdx.x;
    const int tid = threadIdx.x;
    __shared__ float sh[256];

    long long lab;
    if (g_lab_is64) lab = ((const long long*)labels)[b];
    else            lab = (long long)((const int*)labels)[b];
    if (lab < 0) lab = 0;
    if (lab >= NCLASS) lab = NCLASS - 1;

    {
        float2 ev = *(const float2*)&emb[(size_t)b * EMB_D + tid * 2];
        float2 wv = *(const float2*)&weight[(size_t)lab * EMB_D + tid * 2];
        sh[tid] = ev.x * wv.x + ev.y * wv.y;
    }
    __syncthreads();
    for (int o = 128; o > 0; o >>= 1) {
        if (tid < o) sh[tid] += sh[tid + o];
        __syncthreads();
    }
    float dot = sh[0];
    __syncthreads();

    float mx = -FLT_MAX;
    for (int t = tid; t < NTILES; t += 256)
        mx = fmaxf(mx, g_m[(size_t)b * NTILES + t]);
    sh[tid] = mx;
    __syncthreads();
    for (int o = 128; o > 0; o >>= 1) {
        if (tid < o) sh[tid] = fmaxf(sh[tid], sh[tid + o]);
        __syncthreads();
    }
    float M = sh[0];
    __syncthreads();

    float s = 0.f;
    for (int t = tid; t < NTILES; t += 256)
        s += g_s[(size_t)b * NTILES + t] * __expf(g_m[(size_t)b * NTILES + t] - M);
    sh[tid] = s;
    __syncthreads();
    for (int o = 128; o > 0; o >>= 1) {
        if (tid < o) sh[tid] += sh[tid + o];
        __syncthreads();
    }

    if (tid == 0) {
        float S  = sh[0];
        float cv = dot * g_inv_norm[lab] * (1.0f / SCALE_F);
        float l_cos = SCALE_F * cv;
        float sine  = sqrtf(fmaxf(0.f, fminf(1.f, 1.f - cv * cv)));
        float phi   = cv * COS_M - sine * SIN_M;
        if (!(cv > TH_C)) phi = cv - MM_C;
        float l_phi = SCALE_F * phi;
        float Sc = S - expf(l_cos - M) + expf(l_phi - M);
        g_nll[b] = M + logf(Sc) - l_phi;
    }
}

// ---------------------------------------------------------------------------
// Kernel 4: mean -> scalar.
// ---------------------------------------------------------------------------
__global__ __launch_bounds__(256) void mean_kernel(float* __restrict__ out) {
    const int tid = threadIdx.x;
    __shared__ float sh[256];
    float s = 0.f;
    for (int i = tid; i < B_ROWS; i += 256) s += g_nll[i];
    sh[tid] = s;
    __syncthreads();
    for (int o = 128; o > 0; o >>= 1) {
        if (tid < o) sh[tid] += sh[tid + o];
        __syncthreads();
    }
    if (tid == 0) out[0] = sh[0] * (1.0f / (float)B_ROWS);
}

// ---------------------------------------------------------------------------
extern "C" void kernel_launch(void* const* d_in, const int* in_sizes, int n_in,
                              void* d_out, int out_size) {
    const float* emb    = (const float*)d_in[0];
    const void*  labels = d_in[1];
    const float* weight = (const float*)d_in[2];
    float*       out    = (float*)d_out;

    cudaFuncSetAttribute(gemm_lse_h, cudaFuncAttributeMaxDynamicSharedMemorySize, SMEM_DYN);

    detect_labels_kernel<<<1, 512>>>(labels);
    norm_convert_w<<<(NCLASS + 7) / 8, 256>>>(weight);
    convert_e<<<B_ROWS * EMB_D / 4 / 256, 256>>>(emb);

    dim3 grid(8, NPAIRS);
    gemm_lse_h<<<grid, 512, SMEM_DYN>>>();

    finalize_rows_kernel<<<B_ROWS, 256>>>(emb, labels, weight);
    mean_kernel<<<1, 256>>>(out);
}

// round 12
// speedup vs baseline: 1.3808x; 1.1145x over previous
#include <cuda_runtime.h>
#include <cuda_fp16.h>
#include <math.h>
#include <float.h>
#include <stdint.h>

// ---------------- problem constants ----------------
#define B_ROWS   1024
#define EMB_D    512
#define NCLASS   100000
#define CT       128                              // class tile (N)
#define NTILES   ((NCLASS + CT - 1) / CT)         // 782
#define MBLK     8                                // B_ROWS / 128
#define SCALE_F  30.0f

// ArcFace margin constants (margin = 0.3)
#define COS_M 0.9553364891256061f
#define SIN_M 0.2955202066613396f
#define TH_C  (-0.9553364891256061f)
#define MM_C  0.08865606199840186f

// ---------------- scratch ----------------
__device__ __half g_wh[(size_t)NCLASS * EMB_D];   // fp16 weight, 30/||w|| folded
__device__ __half g_eh[B_ROWS * EMB_D];           // fp16 embeddings
__device__ float  g_inv_norm[NCLASS];             // 30/||w|| (exact label path)
__device__ float  g_m[B_ROWS * NTILES];
__device__ float  g_s[B_ROWS * NTILES];
__device__ float  g_nll[B_ROWS];
__device__ int    g_lab_is64;

// ---------------- helpers ----------------
__device__ __forceinline__ uint32_t smem_u32(const void* p) {
    uint32_t a;
    asm("{ .reg .u64 t; cvta.to.shared.u64 t, %1; cvt.u32.u64 %0, t; }" : "=r"(a) : "l"(p));
    return a;
}
__device__ __forceinline__ void cp16(uint32_t dst, const void* src, int bytes) {
    asm volatile("cp.async.cg.shared.global [%0], [%1], 16, %2;" :: "r"(dst), "l"(src), "r"(bytes));
}
#define CP_COMMIT()  asm volatile("cp.async.commit_group;" ::: "memory")
#define CP_WAIT(n)   asm volatile("cp.async.wait_group %0;" :: "n"(n) : "memory")

__device__ __forceinline__ void mma_16816(float* c, const uint32_t* a, uint32_t b0, uint32_t b1) {
    asm volatile(
        "mma.sync.aligned.m16n8k16.row.col.f32.f16.f16.f32 "
        "{%0,%1,%2,%3}, {%4,%5,%6,%7}, {%8,%9}, {%0,%1,%2,%3};"
        : "+f"(c[0]), "+f"(c[1]), "+f"(c[2]), "+f"(c[3])
        : "r"(a[0]), "r"(a[1]), "r"(a[2]), "r"(a[3]), "r"(b0), "r"(b1));
}
__device__ __forceinline__ void ldm_x4(uint32_t* r, uint32_t addr) {
    asm volatile("ldmatrix.sync.aligned.m8n8.x4.shared.b16 {%0,%1,%2,%3}, [%4];"
                 : "=r"(r[0]), "=r"(r[1]), "=r"(r[2]), "=r"(r[3]) : "r"(addr));
}

// smem geometry: fp16, K-chunk 64, padded row stride 72 halves (144 B)
// stage = A(128 rows) + B(128 rows); 3-stage ring, 1 barrier per chunk.
#define RS_H        72
#define TILE_B      (128 * RS_H * 2)               // 18432 B per operand
#define STAGE_B     (2 * TILE_B)                   // 36864 B
#define NSTAGE      3
#define PART_OFF    (NSTAGE * STAGE_B)             // 110592
#define SMEM_DYN    (PART_OFF + 2048)              // 112640 B (2 CTAs/SM: 220 KB)

// ---------------------------------------------------------------------------
// Kernel A: probe labels dtype (int64 vs int32 under JAX x64-off).
// ---------------------------------------------------------------------------
__global__ __launch_bounds__(512) void detect_labels_kernel(const void* __restrict__ labels) {
    __shared__ int bad;
    if (threadIdx.x == 0) bad = 0;
    __syncthreads();
    long long v = ((const long long*)labels)[threadIdx.x];
    if (v < 0 || v >= NCLASS) atomicOr(&bad, 1);
    __syncthreads();
    if (threadIdx.x == 0) g_lab_is64 = bad ? 0 : 1;
}

// ---------------------------------------------------------------------------
// Kernel 0: fused per-class norm + fp16 convert (30/||w|| folded).
// ---------------------------------------------------------------------------
__global__ __launch_bounds__(256) void norm_convert_w(const float* __restrict__ weight) {
    int gid  = blockIdx.x * blockDim.x + threadIdx.x;
    int c    = gid >> 5;
    int lane = gid & 31;
    if (c >= NCLASS) return;
    const float* w = weight + (size_t)c * EMB_D;
    float4 v[4];
    float s = 0.f;
    #pragma unroll
    for (int i = 0; i < 4; i++) {
        v[i] = *(const float4*)&w[lane * 4 + i * 128];
        s += v[i].x * v[i].x + v[i].y * v[i].y + v[i].z * v[i].z + v[i].w * v[i].w;
    }
    #pragma unroll
    for (int o = 16; o > 0; o >>= 1) s += __shfl_xor_sync(0xffffffffu, s, o);
    float sc = SCALE_F * rsqrtf(s);
    if (lane == 0) g_inv_norm[c] = sc;
    __half* dst = g_wh + (size_t)c * EMB_D;
    #pragma unroll
    for (int i = 0; i < 4; i++) {
        __half2 h0 = __floats2half2_rn(v[i].x * sc, v[i].y * sc);
        __half2 h1 = __floats2half2_rn(v[i].z * sc, v[i].w * sc);
        *(uint2*)&dst[lane * 4 + i * 128] = make_uint2(*(uint32_t*)&h0, *(uint32_t*)&h1);
    }
}

// ---------------------------------------------------------------------------
// Kernel 0b: embeddings fp32 -> fp16.
// ---------------------------------------------------------------------------
__global__ __launch_bounds__(256) void convert_e(const float* __restrict__ emb) {
    int i = blockIdx.x * blockDim.x + threadIdx.x;
    float4 v = *(const float4*)&emb[i * 4];
    __half2 h0 = __floats2half2_rn(v.x, v.y);
    __half2 h1 = __floats2half2_rn(v.z, v.w);
    *(uint2*)&g_eh[i * 4] = make_uint2(*(uint32_t*)&h0, *(uint32_t*)&h1);
}

// ---------------------------------------------------------------------------
// Kernel 1: fp16 mma GEMM 128x128x512 + fused logsumexp.
// grid=(MBLK, NTILES), 256 threads (8 warps: 4M x 2N), warp tile 32x64,
// 3-stage cp.async ring -> ONE __syncthreads per K-chunk, 2 CTAs/SM.
// ---------------------------------------------------------------------------
__global__ __launch_bounds__(256, 2) void gemm_lse_h(void) {
    extern __shared__ __align__(16) char smc[];
    float*  sm_pm = (float*)(smc + PART_OFF);          // [128][2]
    float*  sm_ps = sm_pm + 256;

    const int tid    = threadIdx.x;
    const int m_base = blockIdx.x * 128;
    const int c0     = blockIdx.y * CT;

    const int wid  = tid >> 5, lane = tid & 31;
    const int wm   = wid & 3;
    const int wn   = wid >> 2;
    const int g    = lane >> 2, tig = lane & 3;

    const uint32_t smem_base = smem_u32(smc);

    // ldmatrix per-lane byte offsets within a stage
    const uint32_t a_off = ((uint32_t)(wm * 32 + (lane & 7) + ((lane >> 3) & 1) * 8) * RS_H
                            + ((lane >> 4) & 1) * 8) * 2;
    const uint32_t b_off = (uint32_t)TILE_B
                         + ((uint32_t)(wn * 64 + (lane & 7) + ((lane >> 4) & 1) * 8) * RS_H
                            + ((lane >> 3) & 1) * 8) * 2;

    // stage fill: 256 rows x 8 x 16B units = 2048 cp16, 8 per thread.
    auto load_stage = [&](int kt, int stage) {
        const int k0 = kt * 64;
        const uint32_t sa = smem_base + stage * STAGE_B;
        const uint32_t sb = sa + TILE_B;
        #pragma unroll
        for (int i = 0; i < 8; i++) {
            int id = tid + i * 256;              // 0..2047
            int r  = id >> 3;                    // 0..255
            int u  = id & 7;                     // 16B unit
            if (r < 128) {
                cp16(sa + (r * RS_H + u * 8) * 2,
                     g_eh + (size_t)(m_base + r) * EMB_D + k0 + u * 8, 16);
            } else {
                int rr = r - 128;
                int c  = c0 + rr;
                int cc = (c < NCLASS) ? c : (NCLASS - 1);
                cp16(sb + (rr * RS_H + u * 8) * 2,
                     g_wh + (size_t)cc * EMB_D + k0 + u * 8,
                     (c < NCLASS) ? 16 : 0);
            }
        }
        CP_COMMIT();
    };

    float acc[2][8][4];
    #pragma unroll
    for (int mi = 0; mi < 2; mi++)
        #pragma unroll
        for (int ni = 0; ni < 8; ni++)
            #pragma unroll
            for (int q = 0; q < 4; q++) acc[mi][ni][q] = 0.f;

    load_stage(0, 0);
    load_stage(1, 1);

    #pragma unroll 1
    for (int kt = 0; kt < 8; kt++) {
        if (kt == 7) { CP_WAIT(0); } else { CP_WAIT(1); }
        __syncthreads();
        // prefetch kt+2 into ring slot (kt+2)%3: that slot held chunk kt-1,
        // fully consumed before this barrier (ldmatrix reads are synchronous).
        if (kt + 2 < 8) load_stage(kt + 2, (kt + 2) % NSTAGE);

        const uint32_t sA = smem_base + (uint32_t)(kt % NSTAGE) * STAGE_B + a_off;
        const uint32_t sB = smem_base + (uint32_t)(kt % NSTAGE) * STAGE_B + b_off;

        #pragma unroll
        for (int ks = 0; ks < 4; ks++) {
            const uint32_t kb = (uint32_t)ks * 32;     // 16 halves
            uint32_t a[2][4];
            ldm_x4(a[0], sA + kb);
            ldm_x4(a[1], sA + (16 * RS_H) * 2 + kb);
            #pragma unroll
            for (int nip = 0; nip < 4; nip++) {
                uint32_t br[4];
                ldm_x4(br, sB + (uint32_t)(nip * 16 * RS_H) * 2 + kb);
                mma_16816(acc[0][2 * nip],     a[0], br[0], br[1]);
                mma_16816(acc[1][2 * nip],     a[1], br[0], br[1]);
                mma_16816(acc[0][2 * nip + 1], a[0], br[2], br[3]);
                mma_16816(acc[1][2 * nip + 1], a[1], br[2], br[3]);
            }
        }
    }

    // ---- epilogue: per-row (max, sumexp); scale folded into weights.
    #pragma unroll
    for (int mi = 0; mi < 2; mi++) {
        #pragma unroll
        for (int half = 0; half < 2; half++) {
            const int row = wm * 32 + mi * 16 + half * 8 + g;
            float lv[16];
            float mx = -FLT_MAX;
            #pragma unroll
            for (int ni = 0; ni < 8; ni++) {
                int col = wn * 64 + ni * 8 + 2 * tig;
                float v0 = acc[mi][ni][half * 2 + 0];
                float v1 = acc[mi][ni][half * 2 + 1];
                if (c0 + col     >= NCLASS) v0 = -FLT_MAX;
                if (c0 + col + 1 >= NCLASS) v1 = -FLT_MAX;
                lv[ni * 2]     = v0;
                lv[ni * 2 + 1] = v1;
                mx = fmaxf(mx, fmaxf(v0, v1));
            }
            float ss = 0.f;
            #pragma unroll
            for (int j = 0; j < 16; j++) ss += __expf(lv[j] - mx);
            #pragma unroll
            for (int d = 1; d <= 2; d <<= 1) {
                float om = __shfl_xor_sync(0xffffffffu, mx, d);
                float os = __shfl_xor_sync(0xffffffffu, ss, d);
                float nm = fmaxf(mx, om);
                ss = ss * __expf(mx - nm) + os * __expf(om - nm);
                mx = nm;
            }
            if (tig == 0) {
                sm_pm[row * 2 + wn] = mx;
                sm_ps[row * 2 + wn] = ss;
            }
        }
    }
    __syncthreads();

    if (tid < 128) {
        float m0 = sm_pm[tid * 2], m1 = sm_pm[tid * 2 + 1];
        float s0 = sm_ps[tid * 2], s1 = sm_ps[tid * 2 + 1];
        float M = fmaxf(m0, m1);
        float S = s0 * __expf(m0 - M) + s1 * __expf(m1 - M);
        g_m[(size_t)(m_base + tid) * NTILES + blockIdx.y] = M;
        g_s[(size_t)(m_base + tid) * NTILES + blockIdx.y] = S;
    }
}

// ---------------------------------------------------------------------------
// Kernel 3: combine tile partials + exact label cosine + ArcFace correction.
// ---------------------------------------------------------------------------
__global__ __launch_bounds__(256) void finalize_rows_kernel(const float* __restrict__ emb,
                                                            const void* __restrict__ labels,
                                                            const float* __restrict__ weight) {
    const int b   = blockIdx.x;
    const int tid = threadIdx.x;
    __shared__ float sh[256];

    long long lab;
    if (g_lab_is64) lab = ((const long long*)labels)[b];
    else            lab = (long long)((const int*)labels)[b];
    if (lab < 0) lab = 0;
    if (lab >= NCLASS) lab = NCLASS - 1;

    {
        float2 ev = *(const float2*)&emb[(size_t)b * EMB_D + tid * 2];
        float2 wv = *(const float2*)&weight[(size_t)lab * EMB_D + tid * 2];
        sh[tid] = ev.x * wv.x + ev.y * wv.y;
    }
    __syncthreads();
    for (int o = 128; o > 0; o >>= 1) {
        if (tid < o) sh[tid] += sh[tid + o];
        __syncthreads();
    }
    float dot = sh[0];
    __syncthreads();

    float mx = -FLT_MAX;
    for (int t = tid; t < NTILES; t += 256)
        mx = fmaxf(mx, g_m[(size_t)b * NTILES + t]);
    sh[tid] = mx;
    __syncthreads();
    for (int o = 128; o > 0; o >>= 1) {
        if (tid < o) sh[tid] = fmaxf(sh[tid], sh[tid + o]);
        __syncthreads();
    }
    float M = sh[0];
    __syncthreads();

    float s = 0.f;
    for (int t = tid; t < NTILES; t += 256)
        s += g_s[(size_t)b * NTILES + t] * __expf(g_m[(size_t)b * NTILES + t] - M);
    sh[tid] = s;
    __syncthreads();
    for (int o = 128; o > 0; o >>= 1) {
        if (tid < o) sh[tid] += sh[tid + o];
        __syncthreads();
    }

    if (tid == 0) {
        float S  = sh[0];
        float cv = dot * g_inv_norm[lab] * (1.0f / SCALE_F);
        float l_cos = SCALE_F * cv;
        float sine  = sqrtf(fmaxf(0.f, fminf(1.f, 1.f - cv * cv)));
        float phi   = cv * COS_M - sine * SIN_M;
        if (!(cv > TH_C)) phi = cv - MM_C;
        float l_phi = SCALE_F * phi;
        float Sc = S - expf(l_cos - M) + expf(l_phi - M);
        g_nll[b] = M + logf(Sc) - l_phi;
    }
}

// ---------------------------------------------------------------------------
// Kernel 4: mean -> scalar.
// ---------------------------------------------------------------------------
__global__ __launch_bounds__(256) void mean_kernel(float* __restrict__ out) {
    const int tid = threadIdx.x;
    __shared__ float sh[256];
    float s = 0.f;
    for (int i = tid; i < B_ROWS; i += 256) s += g_nll[i];
    sh[tid] = s;
    __syncthreads();
    for (int o = 128; o > 0; o >>= 1) {
        if (tid < o) sh[tid] += sh[tid + o];
        __syncthreads();
    }
    if (tid == 0) out[0] = sh[0] * (1.0f / (float)B_ROWS);
}

// ---------------------------------------------------------------------------
extern "C" void kernel_launch(void* const* d_in, const int* in_sizes, int n_in,
                              void* d_out, int out_size) {
    const float* emb    = (const float*)d_in[0];
    const void*  labels = d_in[1];
    const float* weight = (const float*)d_in[2];
    float*       out    = (float*)d_out;

    cudaFuncSetAttribute(gemm_lse_h, cudaFuncAttributeMaxDynamicSharedMemorySize, SMEM_DYN);

    detect_labels_kernel<<<1, 512>>>(labels);
    norm_convert_w<<<(NCLASS + 7) / 8, 256>>>(weight);
    convert_e<<<B_ROWS * EMB_D / 4 / 256, 256>>>(emb);

    dim3 grid(MBLK, NTILES);
    gemm_lse_h<<<grid, 256, SMEM_DYN>>>();

    finalize_rows_kernel<<<B_ROWS, 256>>>(emb, labels, weight);
    mean_kernel<<<1, 256>>>(out);
}

// round 13
// speedup vs baseline: 1.3974x; 1.0121x over previous
#include <cuda_runtime.h>
#include <cuda_fp16.h>
#include <math.h>
#include <float.h>
#include <stdint.h>

// ---------------- problem constants ----------------
#define B_ROWS   1024
#define EMB_D    512
#define NCLASS   100000
#define CT       128                              // class tile (N)
#define NTILES   ((NCLASS + CT - 1) / CT)         // 782
#define MBLK     8                                // B_ROWS / 128
#define SCALE_F  30.0f

// ArcFace margin constants (margin = 0.3)
#define COS_M 0.9553364891256061f
#define SIN_M 0.2955202066613396f
#define TH_C  (-0.9553364891256061f)
#define MM_C  0.08865606199840186f

// ---------------- scratch ----------------
__device__ __half g_wh[(size_t)NCLASS * EMB_D];   // fp16 weight, 30/||w|| folded
__device__ __half g_eh[B_ROWS * EMB_D];           // fp16 embeddings
__device__ float  g_inv_norm[NCLASS];             // 30/||w|| (exact label path)
__device__ float  g_m[B_ROWS * NTILES];
__device__ float  g_s[B_ROWS * NTILES];
__device__ float  g_nll[B_ROWS];
__device__ int    g_lab_is64;

// ---------------- helpers ----------------
__device__ __forceinline__ uint32_t smem_u32(const void* p) {
    uint32_t a;
    asm("{ .reg .u64 t; cvta.to.shared.u64 t, %1; cvt.u32.u64 %0, t; }" : "=r"(a) : "l"(p));
    return a;
}
__device__ __forceinline__ void cp16(uint32_t dst, const void* src, int bytes) {
    asm volatile("cp.async.cg.shared.global [%0], [%1], 16, %2;" :: "r"(dst), "l"(src), "r"(bytes));
}
#define CP_COMMIT()  asm volatile("cp.async.commit_group;" ::: "memory")
#define CP_WAIT(n)   asm volatile("cp.async.wait_group %0;" :: "n"(n) : "memory")

__device__ __forceinline__ void mma_16816(float* c, const uint32_t* a, uint32_t b0, uint32_t b1) {
    asm volatile(
        "mma.sync.aligned.m16n8k16.row.col.f32.f16.f16.f32 "
        "{%0,%1,%2,%3}, {%4,%5,%6,%7}, {%8,%9}, {%0,%1,%2,%3};"
        : "+f"(c[0]), "+f"(c[1]), "+f"(c[2]), "+f"(c[3])
        : "r"(a[0]), "r"(a[1]), "r"(a[2]), "r"(a[3]), "r"(b0), "r"(b1));
}
__device__ __forceinline__ void ldm_x4(uint32_t* r, uint32_t addr) {
    asm volatile("ldmatrix.sync.aligned.m8n8.x4.shared.b16 {%0,%1,%2,%3}, [%4];"
                 : "=r"(r[0]), "=r"(r[1]), "=r"(r[2]), "=r"(r[3]) : "r"(addr));
}

// smem geometry: fp16, K-chunk 64, padded row stride 72 halves (144 B)
// stage = A(128 rows) + B(128 rows); 3-stage ring, 1 barrier per chunk.
#define RS_H        72
#define TILE_B      (128 * RS_H * 2)               // 18432 B per operand
#define STAGE_B     (2 * TILE_B)                   // 36864 B
#define NSTAGE      3
#define PART_OFF    (NSTAGE * STAGE_B)             // 110592
#define SMEM_DYN    (PART_OFF + 2048)              // 112640 B (2 CTAs/SM: 220 KB)

// ---------------------------------------------------------------------------
// Kernel A: probe labels dtype (int64 vs int32 under JAX x64-off).
// ---------------------------------------------------------------------------
__global__ __launch_bounds__(512) void detect_labels_kernel(const void* __restrict__ labels) {
    __shared__ int bad;
    if (threadIdx.x == 0) bad = 0;
    __syncthreads();
    long long v = ((const long long*)labels)[threadIdx.x];
    if (v < 0 || v >= NCLASS) atomicOr(&bad, 1);
    __syncthreads();
    if (threadIdx.x == 0) g_lab_is64 = bad ? 0 : 1;
}

// ---------------------------------------------------------------------------
// Kernel 0: fused prepass (one launch):
//  blocks [0, WBLK)       : per-class norm + fp16 convert (30/||w|| folded)
//  blocks [WBLK, WBLK+EB) : embeddings fp32 -> fp16
// ---------------------------------------------------------------------------
#define WBLK ((NCLASS + 7) / 8)                    // 12500
#define EBLK (B_ROWS * EMB_D / 4 / 256)            // 512

__global__ __launch_bounds__(256) void prepass_kernel(const float* __restrict__ weight,
                                                      const float* __restrict__ emb) {
    if (blockIdx.x < WBLK) {
        int gid  = blockIdx.x * 256 + threadIdx.x;
        int c    = gid >> 5;
        int lane = gid & 31;
        if (c >= NCLASS) return;
        const float* w = weight + (size_t)c * EMB_D;
        float4 v[4];
        float s = 0.f;
        #pragma unroll
        for (int i = 0; i < 4; i++) {
            v[i] = *(const float4*)&w[lane * 4 + i * 128];
            s += v[i].x * v[i].x + v[i].y * v[i].y + v[i].z * v[i].z + v[i].w * v[i].w;
        }
        #pragma unroll
        for (int o = 16; o > 0; o >>= 1) s += __shfl_xor_sync(0xffffffffu, s, o);
        float sc = SCALE_F * rsqrtf(s);
        if (lane == 0) g_inv_norm[c] = sc;
        __half* dst = g_wh + (size_t)c * EMB_D;
        #pragma unroll
        for (int i = 0; i < 4; i++) {
            __half2 h0 = __floats2half2_rn(v[i].x * sc, v[i].y * sc);
            __half2 h1 = __floats2half2_rn(v[i].z * sc, v[i].w * sc);
            *(uint2*)&dst[lane * 4 + i * 128] = make_uint2(*(uint32_t*)&h0, *(uint32_t*)&h1);
        }
    } else {
        int i = (blockIdx.x - WBLK) * 256 + threadIdx.x;   // one float4 per thread
        float4 v = *(const float4*)&emb[i * 4];
        __half2 h0 = __floats2half2_rn(v.x, v.y);
        __half2 h1 = __floats2half2_rn(v.z, v.w);
        *(uint2*)&g_eh[i * 4] = make_uint2(*(uint32_t*)&h0, *(uint32_t*)&h1);
    }
}

// ---------------------------------------------------------------------------
// Kernel 1: fp16 mma GEMM 128x128x512 + fused logsumexp.
// grid=(MBLK, NTILES), 256 threads (8 warps: 4M x 2N), warp tile 32x64,
// 3-stage cp.async ring, ONE __syncthreads per K-chunk, 2 CTAs/SM.
// Ring pointers maintained by increment+wrap (no modulo in hot loop);
// CP_WAIT branch peeled out of the steady-state loop.
// ---------------------------------------------------------------------------
__global__ __launch_bounds__(256, 2) void gemm_lse_h(void) {
    extern __shared__ __align__(16) char smc[];
    float*  sm_pm = (float*)(smc + PART_OFF);          // [128][2]
    float*  sm_ps = sm_pm + 256;

    const int tid    = threadIdx.x;
    const int m_base = blockIdx.x * 128;
    const int c0     = blockIdx.y * CT;

    const int wid  = tid >> 5, lane = tid & 31;
    const int wm   = wid & 3;
    const int wn   = wid >> 2;
    const int g    = lane >> 2, tig = lane & 3;

    const uint32_t smem_base = smem_u32(smc);

    // ldmatrix per-lane byte offsets within a stage
    const uint32_t a_off = ((uint32_t)(wm * 32 + (lane & 7) + ((lane >> 3) & 1) * 8) * RS_H
                            + ((lane >> 4) & 1) * 8) * 2;
    const uint32_t b_off = (uint32_t)TILE_B
                         + ((uint32_t)(wn * 64 + (lane & 7) + ((lane >> 4) & 1) * 8) * RS_H
                            + ((lane >> 3) & 1) * 8) * 2;

    // stage fill: 256 rows x 8 x 16B units = 2048 cp16, 8 per thread.
    auto load_stage = [&](int kt, uint32_t sa) {
        const int k0 = kt * 64;
        const uint32_t sb = sa + TILE_B;
        #pragma unroll
        for (int i = 0; i < 8; i++) {
            int id = tid + i * 256;              // 0..2047
            int r  = id >> 3;                    // 0..255
            int u  = id & 7;                     // 16B unit
            if (r < 128) {
                cp16(sa + (r * RS_H + u * 8) * 2,
                     g_eh + (size_t)(m_base + r) * EMB_D + k0 + u * 8, 16);
            } else {
                int rr = r - 128;
                int c  = c0 + rr;
                int cc = (c < NCLASS) ? c : (NCLASS - 1);
                cp16(sb + (rr * RS_H + u * 8) * 2,
                     g_wh + (size_t)cc * EMB_D + k0 + u * 8,
                     (c < NCLASS) ? 16 : 0);
            }
        }
        CP_COMMIT();
    };

    float acc[2][8][4];
    #pragma unroll
    for (int mi = 0; mi < 2; mi++)
        #pragma unroll
        for (int ni = 0; ni < 8; ni++)
            #pragma unroll
            for (int q = 0; q < 4; q++) acc[mi][ni][q] = 0.f;

    // consume one chunk resident at stage base 'cur' (absolute smem address)
    auto consume = [&](uint32_t cur) {
        const uint32_t sA = cur + a_off;
        const uint32_t sB = cur + b_off;
        #pragma unroll
        for (int ks = 0; ks < 4; ks++) {
            const uint32_t kb = (uint32_t)ks * 32;     // 16 halves
            uint32_t a[2][4];
            ldm_x4(a[0], sA + kb);
            ldm_x4(a[1], sA + (16 * RS_H) * 2 + kb);
            #pragma unroll
            for (int nip = 0; nip < 4; nip++) {
                uint32_t br[4];
                ldm_x4(br, sB + (uint32_t)(nip * 16 * RS_H) * 2 + kb);
                mma_16816(acc[0][2 * nip],     a[0], br[0], br[1]);
                mma_16816(acc[1][2 * nip],     a[1], br[0], br[1]);
                mma_16816(acc[0][2 * nip + 1], a[0], br[2], br[3]);
                mma_16816(acc[1][2 * nip + 1], a[1], br[2], br[3]);
            }
        }
    };

    const uint32_t ring_end = smem_base + NSTAGE * STAGE_B;
    uint32_t cur = smem_base;                    // stage of chunk kt
    uint32_t pf  = smem_base + 2 * STAGE_B;      // stage for chunk kt+2

    load_stage(0, smem_base);
    load_stage(1, smem_base + STAGE_B);

    // steady state: kt = 0..5 (prefetch kt+2 exists)
    #pragma unroll 1
    for (int kt = 0; kt < 6; kt++) {
        CP_WAIT(1);
        __syncthreads();
        load_stage(kt + 2, pf);                  // slot held chunk kt-1 (consumed)
        consume(cur);
        cur += STAGE_B; if (cur == ring_end) cur = smem_base;
        pf  += STAGE_B; if (pf  == ring_end) pf  = smem_base;
    }
    // kt = 6: one fill still in flight
    CP_WAIT(1);
    __syncthreads();
    consume(cur);
    cur += STAGE_B; if (cur == ring_end) cur = smem_base;
    // kt = 7: drain
    CP_WAIT(0);
    __syncthreads();
    consume(cur);

    // ---- epilogue: per-row (max, sumexp); scale folded into weights.
    #pragma unroll
    for (int mi = 0; mi < 2; mi++) {
        #pragma unroll
        for (int half = 0; half < 2; half++) {
            const int row = wm * 32 + mi * 16 + half * 8 + g;
            float lv[16];
            float mx = -FLT_MAX;
            #pragma unroll
            for (int ni = 0; ni < 8; ni++) {
                int col = wn * 64 + ni * 8 + 2 * tig;
                float v0 = acc[mi][ni][half * 2 + 0];
                float v1 = acc[mi][ni][half * 2 + 1];
                if (c0 + col     >= NCLASS) v0 = -FLT_MAX;
                if (c0 + col + 1 >= NCLASS) v1 = -FLT_MAX;
                lv[ni * 2]     = v0;
                lv[ni * 2 + 1] = v1;
                mx = fmaxf(mx, fmaxf(v0, v1));
            }
            float ss = 0.f;
            #pragma unroll
            for (int j = 0; j < 16; j++) ss += __expf(lv[j] - mx);
            #pragma unroll
            for (int d = 1; d <= 2; d <<= 1) {
                float om = __shfl_xor_sync(0xffffffffu, mx, d);
                float os = __shfl_xor_sync(0xffffffffu, ss, d);
                float nm = fmaxf(mx, om);
                ss = ss * __expf(mx - nm) + os * __expf(om - nm);
                mx = nm;
            }
            if (tig == 0) {
                sm_pm[row * 2 + wn] = mx;
                sm_ps[row * 2 + wn] = ss;
            }
        }
    }
    __syncthreads();

    if (tid < 128) {
        float m0 = sm_pm[tid * 2], m1 = sm_pm[tid * 2 + 1];
        float s0 = sm_ps[tid * 2], s1 = sm_ps[tid * 2 + 1];
        float M = fmaxf(m0, m1);
        float S = s0 * __expf(m0 - M) + s1 * __expf(m1 - M);
        g_m[(size_t)(m_base + tid) * NTILES + blockIdx.y] = M;
        g_s[(size_t)(m_base + tid) * NTILES + blockIdx.y] = S;
    }
}

// ---------------------------------------------------------------------------
// Kernel 3: combine tile partials + exact label cosine + ArcFace correction.
// ---------------------------------------------------------------------------
__global__ __launch_bounds__(256) void finalize_rows_kernel(const float* __restrict__ emb,
                                                            const void* __restrict__ labels,
                                                            const float* __restrict__ weight) {
    const int b   = blockIdx.x;
    const int tid = threadIdx.x;
    __shared__ float sh[256];

    long long lab;
    if (g_lab_is64) lab = ((const long long*)labels)[b];
    else            lab = (long long)((const int*)labels)[b];
    if (lab < 0) lab = 0;
    if (lab >= NCLASS) lab = NCLASS - 1;

    {
        float2 ev = *(const float2*)&emb[(size_t)b * EMB_D + tid * 2];
        float2 wv = *(const float2*)&weight[(size_t)lab * EMB_D + tid * 2];
        sh[tid] = ev.x * wv.x + ev.y * wv.y;
    }
    __syncthreads();
    for (int o = 128; o > 0; o >>= 1) {
        if (tid < o) sh[tid] += sh[tid + o];
        __syncthreads();
    }
    float dot = sh[0];
    __syncthreads();

    float mx = -FLT_MAX;
    for (int t = tid; t < NTILES; t += 256)
        mx = fmaxf(mx, g_m[(size_t)b * NTILES + t]);
    sh[tid] = mx;
    __syncthreads();
    for (int o = 128; o > 0; o >>= 1) {
        if (tid < o) sh[tid] = fmaxf(sh[tid], sh[tid + o]);
        __syncthreads();
    }
    float M = sh[0];
    __syncthreads();

    float s = 0.f;
    for (int t = tid; t < NTILES; t += 256)
        s += g_s[(size_t)b * NTILES + t] * __expf(g_m[(size_t)b * NTILES + t] - M);
    sh[tid] = s;
    __syncthreads();
    for (int o = 128; o > 0; o >>= 1) {
        if (tid < o) sh[tid] += sh[tid + o];
        __syncthreads();
    }

    if (tid == 0) {
        float S  = sh[0];
        float cv = dot * g_inv_norm[lab] * (1.0f / SCALE_F);
        float l_cos = SCALE_F * cv;
        float sine  = sqrtf(fmaxf(0.f, fminf(1.f, 1.f - cv * cv)));
        float phi   = cv * COS_M - sine * SIN_M;
        if (!(cv > TH_C)) phi = cv - MM_C;
        float l_phi = SCALE_F * phi;
        float Sc = S - expf(l_cos - M) + expf(l_phi - M);
        g_nll[b] = M + logf(Sc) - l_phi;
    }
}

// ---------------------------------------------------------------------------
// Kernel 4: mean -> scalar.
// ---------------------------------------------------------------------------
__global__ __launch_bounds__(256) void mean_kernel(float* __restrict__ out) {
    const int tid = threadIdx.x;
    __shared__ float sh[256];
    float s = 0.f;
    for (int i = tid; i < B_ROWS; i += 256) s += g_nll[i];
    sh[tid] = s;
    __syncthreads();
    for (int o = 128; o > 0; o >>= 1) {
        if (tid < o) sh[tid] += sh[tid + o];
        __syncthreads();
    }
    if (tid == 0) out[0] = sh[0] * (1.0f / (float)B_ROWS);
}

// ---------------------------------------------------------------------------
extern "C" void kernel_launch(void* const* d_in, const int* in_sizes, int n_in,
                              void* d_out, int out_size) {
    const float* emb    = (const float*)d_in[0];
    const void*  labels = d_in[1];
    const float* weight = (const float*)d_in[2];
    float*       out    = (float*)d_out;

    cudaFuncSetAttribute(gemm_lse_h, cudaFuncAttributeMaxDynamicSharedMemorySize, SMEM_DYN);

    detect_labels_kernel<<<1, 512>>>(labels);
    prepass_kernel<<<WBLK + EBLK, 256>>>(weight, emb);

    dim3 grid(MBLK, NTILES);
    gemm_lse_h<<<grid, 256, SMEM_DYN>>>();

    finalize_rows_kernel<<<B_ROWS, 256>>>(emb, labels, weight);
    mean_kernel<<<1, 256>>>(out);
}

// round 14
// speedup vs baseline: 1.4447x; 1.0338x over previous
#include <cuda_runtime.h>
#include <cuda_fp16.h>
#include <math.h>
#include <float.h>
#include <stdint.h>

// ---------------- problem constants ----------------
#define B_ROWS   1024
#define EMB_D    512
#define NCLASS   100000
#define CT       128                              // class tile (N)
#define NTILES   ((NCLASS + CT - 1) / CT)         // 782
#define MBLK     8                                // B_ROWS / 128
#define SCALE_F  30.0f
#define LOG2E_F  1.4426950408889634f
#define LN2_F    0.6931471805599453f

// ArcFace margin constants (margin = 0.3)
#define COS_M 0.9553364891256061f
#define SIN_M 0.2955202066613396f
#define TH_C  (-0.9553364891256061f)
#define MM_C  0.08865606199840186f

// ---------------- scratch ----------------
// g_wh holds weight * (30*log2(e)/||w||): GEMM accumulators are log2-logits.
__device__ __half g_wh[(size_t)NCLASS * EMB_D];
__device__ __half g_eh[B_ROWS * EMB_D];           // fp16 embeddings
__device__ float  g_inv_norm[NCLASS];             // 30/||w|| (exact label path)
__device__ float  g_m[B_ROWS * NTILES];           // per-tile max (log2 domain)
__device__ float  g_s[B_ROWS * NTILES];           // per-tile sum 2^(l-m)
__device__ float  g_nll[B_ROWS];
__device__ int    g_lab_is64;

// ---------------- helpers ----------------
__device__ __forceinline__ uint32_t smem_u32(const void* p) {
    uint32_t a;
    asm("{ .reg .u64 t; cvta.to.shared.u64 t, %1; cvt.u32.u64 %0, t; }" : "=r"(a) : "l"(p));
    return a;
}
__device__ __forceinline__ void cp16(uint32_t dst, const void* src, int bytes) {
    asm volatile("cp.async.cg.shared.global [%0], [%1], 16, %2;" :: "r"(dst), "l"(src), "r"(bytes));
}
__device__ __forceinline__ void cp16u(uint32_t dst, const void* src) {
    asm volatile("cp.async.cg.shared.global [%0], [%1], 16;" :: "r"(dst), "l"(src));
}
#define CP_COMMIT()  asm volatile("cp.async.commit_group;" ::: "memory")
#define CP_WAIT(n)   asm volatile("cp.async.wait_group %0;" :: "n"(n) : "memory")

__device__ __forceinline__ void mma_16816(float* c, const uint32_t* a, uint32_t b0, uint32_t b1) {
    asm volatile(
        "mma.sync.aligned.m16n8k16.row.col.f32.f16.f16.f32 "
        "{%0,%1,%2,%3}, {%4,%5,%6,%7}, {%8,%9}, {%0,%1,%2,%3};"
        : "+f"(c[0]), "+f"(c[1]), "+f"(c[2]), "+f"(c[3])
        : "r"(a[0]), "r"(a[1]), "r"(a[2]), "r"(a[3]), "r"(b0), "r"(b1));
}
__device__ __forceinline__ void ldm_x4(uint32_t* r, uint32_t addr) {
    asm volatile("ldmatrix.sync.aligned.m8n8.x4.shared.b16 {%0,%1,%2,%3}, [%4];"
                 : "=r"(r[0]), "=r"(r[1]), "=r"(r[2]), "=r"(r[3]) : "r"(addr));
}

// smem geometry: fp16, K-chunk 64, padded row stride 72 halves (144 B)
// stage = A(128 rows) + B(128 rows); 3-stage ring, 1 barrier per chunk.
#define RS_H        72
#define TILE_B      (128 * RS_H * 2)               // 18432 B per operand
#define STAGE_B     (2 * TILE_B)                   // 36864 B
#define NSTAGE      3
#define PART_OFF    (NSTAGE * STAGE_B)             // 110592
#define SMEM_DYN    (PART_OFF + 2048)              // 112640 B (2 CTAs/SM: 220 KB)

// ---------------------------------------------------------------------------
// Kernel A: probe labels dtype (int64 vs int32 under JAX x64-off).
// ---------------------------------------------------------------------------
__global__ __launch_bounds__(512) void detect_labels_kernel(const void* __restrict__ labels) {
    __shared__ int bad;
    if (threadIdx.x == 0) bad = 0;
    __syncthreads();
    long long v = ((const long long*)labels)[threadIdx.x];
    if (v < 0 || v >= NCLASS) atomicOr(&bad, 1);
    __syncthreads();
    if (threadIdx.x == 0) g_lab_is64 = bad ? 0 : 1;
}

// ---------------------------------------------------------------------------
// Kernel 0: fused prepass (one launch):
//  blocks [0, WBLK)       : per-class norm + fp16 convert (30*log2e/||w|| folded)
//  blocks [WBLK, WBLK+EB) : embeddings fp32 -> fp16
// ---------------------------------------------------------------------------
#define WBLK ((NCLASS + 7) / 8)                    // 12500
#define EBLK (B_ROWS * EMB_D / 4 / 256)            // 512

__global__ __launch_bounds__(256) void prepass_kernel(const float* __restrict__ weight,
                                                      const float* __restrict__ emb) {
    if (blockIdx.x < WBLK) {
        int gid  = blockIdx.x * 256 + threadIdx.x;
        int c    = gid >> 5;
        int lane = gid & 31;
        if (c >= NCLASS) return;
        const float* w = weight + (size_t)c * EMB_D;
        float4 v[4];
        float s = 0.f;
        #pragma unroll
        for (int i = 0; i < 4; i++) {
            v[i] = *(const float4*)&w[lane * 4 + i * 128];
            s += v[i].x * v[i].x + v[i].y * v[i].y + v[i].z * v[i].z + v[i].w * v[i].w;
        }
        #pragma unroll
        for (int o = 16; o > 0; o >>= 1) s += __shfl_xor_sync(0xffffffffu, s, o);
        float r  = rsqrtf(s);
        if (lane == 0) g_inv_norm[c] = SCALE_F * r;
        float sc = SCALE_F * LOG2E_F * r;          // log2-domain fold
        __half* dst = g_wh + (size_t)c * EMB_D;
        #pragma unroll
        for (int i = 0; i < 4; i++) {
            __half2 h0 = __floats2half2_rn(v[i].x * sc, v[i].y * sc);
            __half2 h1 = __floats2half2_rn(v[i].z * sc, v[i].w * sc);
            *(uint2*)&dst[lane * 4 + i * 128] = make_uint2(*(uint32_t*)&h0, *(uint32_t*)&h1);
        }
    } else {
        int i = (blockIdx.x - WBLK) * 256 + threadIdx.x;   // one float4 per thread
        float4 v = *(const float4*)&emb[i * 4];
        __half2 h0 = __floats2half2_rn(v.x, v.y);
        __half2 h1 = __floats2half2_rn(v.z, v.w);
        *(uint2*)&g_eh[i * 4] = make_uint2(*(uint32_t*)&h0, *(uint32_t*)&h1);
    }
}

// ---------------------------------------------------------------------------
// Kernel 1: fp16 mma GEMM 128x128x512 + fused logsumexp (log2 domain).
// grid=(MBLK, NTILES), 256 threads (8 warps: 4M x 2N), warp tile 32x64,
// 3-stage cp.async ring, ONE __syncthreads per K-chunk, 2 CTAs/SM.
// Full class tiles (781/782) use unguarded fills + unmasked epilogue.
// ---------------------------------------------------------------------------
__global__ __launch_bounds__(256, 2) void gemm_lse_h(void) {
    extern __shared__ __align__(16) char smc[];
    float*  sm_pm = (float*)(smc + PART_OFF);          // [128][2]
    float*  sm_ps = sm_pm + 256;

    const int tid    = threadIdx.x;
    const int m_base = blockIdx.x * 128;
    const int c0     = blockIdx.y * CT;
    const bool full  = (c0 + CT) <= NCLASS;            // uniform per CTA

    const int wid  = tid >> 5, lane = tid & 31;
    const int wm   = wid & 3;
    const int wn   = wid >> 2;
    const int g    = lane >> 2, tig = lane & 3;

    const uint32_t smem_base = smem_u32(smc);

    // ldmatrix per-lane byte offsets within a stage
    const uint32_t a_off = ((uint32_t)(wm * 32 + (lane & 7) + ((lane >> 3) & 1) * 8) * RS_H
                            + ((lane >> 4) & 1) * 8) * 2;
    const uint32_t b_off = (uint32_t)TILE_B
                         + ((uint32_t)(wn * 64 + (lane & 7) + ((lane >> 4) & 1) * 8) * RS_H
                            + ((lane >> 3) & 1) * 8) * 2;

    // per-thread fill coordinates (A/B loops statically split)
    const int fr = tid >> 3;                     // base row 0..31
    const int fu = tid & 7;                      // 16B unit
    const __half* eA = g_eh + (size_t)(m_base + fr) * EMB_D + fu * 8;

    auto load_stage = [&](int kt, uint32_t sa) {
        const int k0 = kt * 64;
        const uint32_t sb = sa + TILE_B;
        #pragma unroll
        for (int i = 0; i < 4; i++) {                       // A rows fr+32i
            cp16u(sa + ((fr + i * 32) * RS_H + fu * 8) * 2,
                  eA + (size_t)(i * 32) * EMB_D + k0);
        }
        if (full) {
            #pragma unroll
            for (int i = 0; i < 4; i++) {                   // B rows fr+32i, no guards
                int rr = fr + i * 32;
                cp16u(sb + (rr * RS_H + fu * 8) * 2,
                      g_wh + (size_t)(c0 + rr) * EMB_D + k0 + fu * 8);
            }
        } else {
            #pragma unroll
            for (int i = 0; i < 4; i++) {
                int rr = fr + i * 32;
                int c  = c0 + rr;
                int cc = (c < NCLASS) ? c : (NCLASS - 1);
                cp16(sb + (rr * RS_H + fu * 8) * 2,
                     g_wh + (size_t)cc * EMB_D + k0 + fu * 8,
                     (c < NCLASS) ? 16 : 0);
            }
        }
        CP_COMMIT();
    };

    float acc[2][8][4];
    #pragma unroll
    for (int mi = 0; mi < 2; mi++)
        #pragma unroll
        for (int ni = 0; ni < 8; ni++)
            #pragma unroll
            for (int q = 0; q < 4; q++) acc[mi][ni][q] = 0.f;

    auto consume = [&](uint32_t cur) {
        const uint32_t sA = cur + a_off;
        const uint32_t sB = cur + b_off;
        #pragma unroll
        for (int ks = 0; ks < 4; ks++) {
            const uint32_t kb = (uint32_t)ks * 32;     // 16 halves
            uint32_t a[2][4];
            ldm_x4(a[0], sA + kb);
            ldm_x4(a[1], sA + (16 * RS_H) * 2 + kb);
            #pragma unroll
            for (int nip = 0; nip < 4; nip++) {
                uint32_t br[4];
                ldm_x4(br, sB + (uint32_t)(nip * 16 * RS_H) * 2 + kb);
                mma_16816(acc[0][2 * nip],     a[0], br[0], br[1]);
                mma_16816(acc[1][2 * nip],     a[1], br[0], br[1]);
                mma_16816(acc[0][2 * nip + 1], a[0], br[2], br[3]);
                mma_16816(acc[1][2 * nip + 1], a[1], br[2], br[3]);
            }
        }
    };

    const uint32_t ring_end = smem_base + NSTAGE * STAGE_B;
    uint32_t cur = smem_base;                    // stage of chunk kt
    uint32_t pf  = smem_base + 2 * STAGE_B;      // stage for chunk kt+2

    load_stage(0, smem_base);
    load_stage(1, smem_base + STAGE_B);

    #pragma unroll 1
    for (int kt = 0; kt < 6; kt++) {
        CP_WAIT(1);
        __syncthreads();
        load_stage(kt + 2, pf);                  // slot held chunk kt-1 (consumed)
        consume(cur);
        cur += STAGE_B; if (cur == ring_end) cur = smem_base;
        pf  += STAGE_B; if (pf  == ring_end) pf  = smem_base;
    }
    CP_WAIT(1);
    __syncthreads();
    consume(cur);
    cur += STAGE_B; if (cur == ring_end) cur = smem_base;
    CP_WAIT(0);
    __syncthreads();
    consume(cur);

    // ---- epilogue: per-row (max, sum 2^) in log2 domain.
    #pragma unroll
    for (int mi = 0; mi < 2; mi++) {
        #pragma unroll
        for (int half = 0; half < 2; half++) {
            const int row = wm * 32 + mi * 16 + half * 8 + g;
            float lv[16];
            float mx = -FLT_MAX;
            #pragma unroll
            for (int ni = 0; ni < 8; ni++) {
                float v0 = acc[mi][ni][half * 2 + 0];
                float v1 = acc[mi][ni][half * 2 + 1];
                if (!full) {
                    int col = wn * 64 + ni * 8 + 2 * tig;
                    if (c0 + col     >= NCLASS) v0 = -FLT_MAX;
                    if (c0 + col + 1 >= NCLASS) v1 = -FLT_MAX;
                }
                lv[ni * 2]     = v0;
                lv[ni * 2 + 1] = v1;
                mx = fmaxf(mx, fmaxf(v0, v1));
            }
            float ss = 0.f;
            #pragma unroll
            for (int j = 0; j < 16; j++) ss += exp2f(lv[j] - mx);
            #pragma unroll
            for (int d = 1; d <= 2; d <<= 1) {
                float om = __shfl_xor_sync(0xffffffffu, mx, d);
                float os = __shfl_xor_sync(0xffffffffu, ss, d);
                float nm = fmaxf(mx, om);
                ss = ss * exp2f(mx - nm) + os * exp2f(om - nm);
                mx = nm;
            }
            if (tig == 0) {
                sm_pm[row * 2 + wn] = mx;
                sm_ps[row * 2 + wn] = ss;
            }
        }
    }
    __syncthreads();

    if (tid < 128) {
        float m0 = sm_pm[tid * 2], m1 = sm_pm[tid * 2 + 1];
        float s0 = sm_ps[tid * 2], s1 = sm_ps[tid * 2 + 1];
        float M = fmaxf(m0, m1);
        float S = s0 * exp2f(m0 - M) + s1 * exp2f(m1 - M);
        g_m[(size_t)(m_base + tid) * NTILES + blockIdx.y] = M;
        g_s[(size_t)(m_base + tid) * NTILES + blockIdx.y] = S;
    }
}

// ---------------------------------------------------------------------------
// Kernel 3: one WARP per batch row (no block barriers): combine tile partials
// + exact label cosine + ArcFace correction. grid = B_ROWS/8, 256 threads.
// ---------------------------------------------------------------------------
__global__ __launch_bounds__(256) void finalize_rows_kernel(const float* __restrict__ emb,
                                                            const void* __restrict__ labels,
                                                            const float* __restrict__ weight) {
    const int wid  = threadIdx.x >> 5;
    const int lane = threadIdx.x & 31;
    const int b    = blockIdx.x * 8 + wid;

    long long lab;
    if (g_lab_is64) lab = ((const long long*)labels)[b];
    else            lab = (long long)((const int*)labels)[b];
    if (lab < 0) lab = 0;
    if (lab >= NCLASS) lab = NCLASS - 1;

    // exact fp32 label dot (fp32 inputs)
    const float* e = emb + (size_t)b * EMB_D;
    const float* w = weight + (size_t)lab * EMB_D;
    float dot = 0.f;
    #pragma unroll
    for (int i = 0; i < 4; i++) {
        float4 ev = *(const float4*)&e[lane * 4 + i * 128];
        float4 wv = *(const float4*)&w[lane * 4 + i * 128];
        dot += ev.x * wv.x + ev.y * wv.y + ev.z * wv.z + ev.w * wv.w;
    }
    #pragma unroll
    for (int o = 16; o > 0; o >>= 1) dot += __shfl_xor_sync(0xffffffffu, dot, o);

    // global max over tiles (log2 domain)
    const float* gm = g_m + (size_t)b * NTILES;
    const float* gs = g_s + (size_t)b * NTILES;
    float M = -FLT_MAX;
    for (int t = lane; t < NTILES; t += 32) M = fmaxf(M, gm[t]);
    #pragma unroll
    for (int o = 16; o > 0; o >>= 1) M = fmaxf(M, __shfl_xor_sync(0xffffffffu, M, o));

    float S = 0.f;
    for (int t = lane; t < NTILES; t += 32) S += gs[t] * exp2f(gm[t] - M);
    #pragma unroll
    for (int o = 16; o > 0; o >>= 1) S += __shfl_xor_sync(0xffffffffu, S, o);

    if (lane == 0) {
        float cv = dot * g_inv_norm[lab] * (1.0f / SCALE_F);     // cosine
        float l_cos = SCALE_F * cv;                              // natural domain
        float sine  = sqrtf(fmaxf(0.f, fminf(1.f, 1.f - cv * cv)));
        float phi   = cv * COS_M - sine * SIN_M;
        if (!(cv > TH_C)) phi = cv - MM_C;
        float l_phi = SCALE_F * phi;
        // swap label's plain term for phi term (log2 domain)
        float Sc = S - exp2f(l_cos * LOG2E_F - M) + exp2f(l_phi * LOG2E_F - M);
        g_nll[b] = (M + log2f(Sc)) * LN2_F - l_phi;
    }
}

// ---------------------------------------------------------------------------
// Kernel 4: mean -> scalar.
// ---------------------------------------------------------------------------
__global__ __launch_bounds__(256) void mean_kernel(float* __restrict__ out) {
    const int tid = threadIdx.x;
    __shared__ float sh[256];
    float s = 0.f;
    for (int i = tid; i < B_ROWS; i += 256) s += g_nll[i];
    sh[tid] = s;
    __syncthreads();
    for (int o = 128; o > 0; o >>= 1) {
        if (tid < o) sh[tid] += sh[tid + o];
        __syncthreads();
    }
    if (tid == 0) out[0] = sh[0] * (1.0f / (float)B_ROWS);
}

// ---------------------------------------------------------------------------
extern "C" void kernel_launch(void* const* d_in, const int* in_sizes, int n_in,
                              void* d_out, int out_size) {
    const float* emb    = (const float*)d_in[0];
    const void*  labels = d_in[1];
    const float* weight = (const float*)d_in[2];
    float*       out    = (float*)d_out;

    cudaFuncSetAttribute(gemm_lse_h, cudaFuncAttributeMaxDynamicSharedMemorySize, SMEM_DYN);

    detect_labels_kernel<<<1, 512>>>(labels);
    prepass_kernel<<<WBLK + EBLK, 256>>>(weight, emb);

    dim3 grid(MBLK, NTILES);
    gemm_lse_h<<<grid, 256, SMEM_DYN>>>();

    finalize_rows_kernel<<<B_ROWS / 8, 256>>>(emb, labels, weight);
    mean_kernel<<<1, 256>>>(out);
}